// round 1
// baseline (speedup 1.0000x reference)
#include <cuda_runtime.h>
#include <math.h>
#include <stdint.h>

#define D_MODEL 1024
#define NHEADS  16
#define DKV     64
#define SEQL    2048
#define BATCH   2
#define MTOT    (BATCH*SEQL)   // 4096

// Scratch (allocation-free rule: __device__ globals)
__device__ float g_q[BATCH*NHEADS*SEQL*DKV];     // [b,h,s,d]
__device__ float g_k[BATCH*NHEADS*SEQL*DKV];
__device__ float g_v[BATCH*NHEADS*SEQL*DKV];
__device__ float g_attn[BATCH*SEQL*D_MODEL];     // [b,s,h*64+d]

// ---------------------------------------------------------------------------
// Projection GEMM: C[m,n] = sum_k A[m,k] * W[n,k]
//   M=4096, N=1024, K=1024.  Block tile 128x128, BK=16, 256 threads, 8x8 micro.
// MODE 0: plain store out[m*1024+n]          (output projection)
// MODE 1: head layout [b,h,s,d] + RoPE       (Q, K)
// MODE 2: head layout [b,h,s,d], no RoPE     (V)
// ---------------------------------------------------------------------------
template<int MODE>
__global__ __launch_bounds__(256)
void proj_kernel(const float* __restrict__ A, const float* __restrict__ W,
                 const int* __restrict__ tpos, float* __restrict__ out)
{
    __shared__ float As[16][132];   // [k][m], padded (132*4B % 16 == 0)
    __shared__ float Bs[16][132];   // [k][n]

    const int tid = threadIdx.x;
    const int tx  = tid & 15;
    const int ty  = tid >> 4;
    const int m0  = blockIdx.y * 128;
    const int n0  = blockIdx.x * 128;

    float acc[8][8];
#pragma unroll
    for (int i = 0; i < 8; i++)
#pragma unroll
        for (int j = 0; j < 8; j++) acc[i][j] = 0.0f;

    const int lrow = tid >> 1;        // 0..127
    const int lkb  = (tid & 1) * 8;   // 0 or 8

    for (int kt = 0; kt < 1024; kt += 16) {
        // Load A tile (transposed into [k][m]) and W tile ([k][n])
        {
            const float4* ap = (const float4*)&A[(size_t)(m0 + lrow) * 1024 + kt + lkb];
            float4 a0 = ap[0], a1 = ap[1];
            As[lkb + 0][lrow] = a0.x; As[lkb + 1][lrow] = a0.y;
            As[lkb + 2][lrow] = a0.z; As[lkb + 3][lrow] = a0.w;
            As[lkb + 4][lrow] = a1.x; As[lkb + 5][lrow] = a1.y;
            As[lkb + 6][lrow] = a1.z; As[lkb + 7][lrow] = a1.w;

            const float4* bp = (const float4*)&W[(size_t)(n0 + lrow) * 1024 + kt + lkb];
            float4 b0 = bp[0], b1 = bp[1];
            Bs[lkb + 0][lrow] = b0.x; Bs[lkb + 1][lrow] = b0.y;
            Bs[lkb + 2][lrow] = b0.z; Bs[lkb + 3][lrow] = b0.w;
            Bs[lkb + 4][lrow] = b1.x; Bs[lkb + 5][lrow] = b1.y;
            Bs[lkb + 6][lrow] = b1.z; Bs[lkb + 7][lrow] = b1.w;
        }
        __syncthreads();

#pragma unroll
        for (int k = 0; k < 16; k++) {
            float4 a0 = *(const float4*)&As[k][ty * 4];
            float4 a1 = *(const float4*)&As[k][64 + ty * 4];
            float4 b0 = *(const float4*)&Bs[k][tx * 4];
            float4 b1 = *(const float4*)&Bs[k][64 + tx * 4];
            float av[8] = {a0.x, a0.y, a0.z, a0.w, a1.x, a1.y, a1.z, a1.w};
            float bv[8] = {b0.x, b0.y, b0.z, b0.w, b1.x, b1.y, b1.z, b1.w};
#pragma unroll
            for (int i = 0; i < 8; i++)
#pragma unroll
                for (int j = 0; j < 8; j++)
                    acc[i][j] = fmaf(av[i], bv[j], acc[i][j]);
        }
        __syncthreads();
    }

    // Epilogue
    int rows[8], cols[8];
#pragma unroll
    for (int i = 0; i < 4; i++) {
        rows[i]     = m0 + ty * 4 + i;
        rows[i + 4] = m0 + 64 + ty * 4 + i;
        cols[i]     = n0 + tx * 4 + i;
        cols[i + 4] = n0 + 64 + tx * 4 + i;
    }

    if (MODE == 0) {
#pragma unroll
        for (int i = 0; i < 8; i++)
#pragma unroll
            for (int j = 0; j < 8; j++)
                out[(size_t)rows[i] * 1024 + cols[j]] = acc[i][j];
        return;
    }

#pragma unroll
    for (int i = 0; i < 8; i++) {
        const int m = rows[i];
        const int b = m >> 11;          // /2048
        const int s = m & 2047;
        float p = 0.0f;
        if (MODE == 1) p = (float)tpos[s];
#pragma unroll
        for (int j = 0; j < 8; j += 2) {
            const int c0 = cols[j];             // even column (pair aligned)
            const int h  = c0 >> 6;
            const int dd = c0 & 63;
            float v0 = acc[i][j];
            float v1 = acc[i][j + 1];
            if (MODE == 1) {
                const int jj = dd >> 1;
                float freq = 1.0f / powf(10000.0f, (float)(2 * jj) * (1.0f / 64.0f));
                float sn, cs;
                sincosf(p * freq, &sn, &cs);
                float r0 = v0 * cs - v1 * sn;
                float r1 = v1 * cs + v0 * sn;
                v0 = r0; v1 = r1;
            }
            const int dst = ((b * NHEADS + h) * SEQL + s) * DKV + dd;
            out[dst]     = v0;
            out[dst + 1] = v1;
        }
    }
}

// ---------------------------------------------------------------------------
// Flash attention, fp32, causal. Grid: (qtile=32, bh=32). Block 256 threads.
// 64x64 Q tile per block, iterate KV tiles 0..qtile with online softmax.
// Dynamic smem: Qs[64][68] (d-major), KP[64][68] (K d-major, reused for P
// kc-major), Vs[64][64] (kc-major).
// ---------------------------------------------------------------------------
__global__ __launch_bounds__(256)
void flash_kernel(const float* __restrict__ Q, const float* __restrict__ K,
                  const float* __restrict__ V, float* __restrict__ out)
{
    extern __shared__ float sm[];
    float* Qs = sm;                 // 64*68
    float* KP = sm + 64 * 68;       // 64*68
    float* Vs = KP + 64 * 68;       // 64*64
#define QS(d, r) Qs[(d) * 68 + (r)]
#define KPS(d, r) KP[(d) * 68 + (r)]
#define VS(r, d) Vs[(r) * 64 + (d)]

    const int tid = threadIdx.x;
    const int tx  = tid & 15;
    const int ty  = tid >> 4;
    const int qt  = blockIdx.x;           // 0..31
    const int bh  = blockIdx.y;           // 0..31
    const int b   = bh >> 4;
    const int h   = bh & 15;
    const size_t base = (size_t)bh * SEQL * DKV;
    const int q0  = qt * 64;

    // Load Q tile transposed: Qs[d][r]
    for (int i = tid; i < 4096; i += 256) {
        int r = i >> 6, d = i & 63;
        QS(d, r) = Q[base + (size_t)(q0 + r) * 64 + d];
    }

    float m_i[4], l_i[4], o[4][4];
#pragma unroll
    for (int i = 0; i < 4; i++) {
        m_i[i] = -1e30f; l_i[i] = 0.0f;
#pragma unroll
        for (int j = 0; j < 4; j++) o[i][j] = 0.0f;
    }

    const float scale = 0.125f;   // 1/sqrt(64)

    for (int jt = 0; jt <= qt; jt++) {
        __syncthreads();   // Q ready (iter 0) / previous PV done (iter>0)
        // Load K (transposed, d-major) and V (kc-major)
        for (int i = tid; i < 4096; i += 256) {
            int r = i >> 6, d = i & 63;
            float kv = K[base + (size_t)(jt * 64 + r) * 64 + d];
            float vv = V[base + (size_t)(jt * 64 + r) * 64 + d];
            KPS(d, r) = kv;
            VS(r, d)  = vv;
        }
        __syncthreads();

        // S = Q K^T (4x4 microtile)
        float s[4][4];
#pragma unroll
        for (int i = 0; i < 4; i++)
#pragma unroll
            for (int j = 0; j < 4; j++) s[i][j] = 0.0f;
#pragma unroll 8
        for (int d = 0; d < 64; d++) {
            float4 a = *(const float4*)&QS(d, ty * 4);
            float4 bb = *(const float4*)&KPS(d, tx * 4);
            float av[4] = {a.x, a.y, a.z, a.w};
            float bv[4] = {bb.x, bb.y, bb.z, bb.w};
#pragma unroll
            for (int i = 0; i < 4; i++)
#pragma unroll
                for (int j = 0; j < 4; j++)
                    s[i][j] = fmaf(av[i], bv[j], s[i][j]);
        }

        // scale + causal mask (only diagonal tile)
        if (jt == qt) {
#pragma unroll
            for (int i = 0; i < 4; i++) {
                int qr = ty * 4 + i;
#pragma unroll
                for (int j = 0; j < 4; j++) {
                    int kc = tx * 4 + j;
                    s[i][j] = (kc > qr) ? -1e30f : s[i][j] * scale;
                }
            }
        } else {
#pragma unroll
            for (int i = 0; i < 4; i++)
#pragma unroll
                for (int j = 0; j < 4; j++) s[i][j] *= scale;
        }

        // Online softmax update (rows split across tx: reduce via shfl.xor)
        float p[4][4];
        float alpha[4];
#pragma unroll
        for (int i = 0; i < 4; i++) {
            float mx = fmaxf(fmaxf(s[i][0], s[i][1]), fmaxf(s[i][2], s[i][3]));
            mx = fmaxf(mx, __shfl_xor_sync(0xffffffffu, mx, 1));
            mx = fmaxf(mx, __shfl_xor_sync(0xffffffffu, mx, 2));
            mx = fmaxf(mx, __shfl_xor_sync(0xffffffffu, mx, 4));
            mx = fmaxf(mx, __shfl_xor_sync(0xffffffffu, mx, 8));
            float mn = fmaxf(m_i[i], mx);
            alpha[i] = __expf(m_i[i] - mn);
            m_i[i] = mn;
            float rs = 0.0f;
#pragma unroll
            for (int j = 0; j < 4; j++) {
                p[i][j] = __expf(s[i][j] - mn);
                rs += p[i][j];
            }
            rs += __shfl_xor_sync(0xffffffffu, rs, 1);
            rs += __shfl_xor_sync(0xffffffffu, rs, 2);
            rs += __shfl_xor_sync(0xffffffffu, rs, 4);
            rs += __shfl_xor_sync(0xffffffffu, rs, 8);
            l_i[i] = l_i[i] * alpha[i] + rs;
#pragma unroll
            for (int j = 0; j < 4; j++) o[i][j] *= alpha[i];
        }

        __syncthreads();   // everyone done reading K before P overwrites it
        // Stage P (kc-major): P[kc][r]
#pragma unroll
        for (int i = 0; i < 4; i++)
#pragma unroll
            for (int j = 0; j < 4; j++)
                KPS(tx * 4 + j, ty * 4 + i) = p[i][j];
        __syncthreads();

        // O += P V  (rows = q rows, cols = head dim)
#pragma unroll 8
        for (int kc = 0; kc < 64; kc++) {
            float4 a = *(const float4*)&KPS(kc, ty * 4);
            float4 bb = *(const float4*)&VS(kc, tx * 4);
            float av[4] = {a.x, a.y, a.z, a.w};
            float bv[4] = {bb.x, bb.y, bb.z, bb.w};
#pragma unroll
            for (int i = 0; i < 4; i++)
#pragma unroll
                for (int j = 0; j < 4; j++)
                    o[i][j] = fmaf(av[i], bv[j], o[i][j]);
        }
    }

    // Normalize + store into [b,s,h*64+d]
#pragma unroll
    for (int i = 0; i < 4; i++) {
        float inv = 1.0f / l_i[i];
        int srow = q0 + ty * 4 + i;
        size_t ob = (size_t)(b * SEQL + srow) * 1024 + h * 64;
#pragma unroll
        for (int j = 0; j < 4; j++)
            out[ob + tx * 4 + j] = o[i][j] * inv;
    }
#undef QS
#undef KPS
#undef VS
}

// ---------------------------------------------------------------------------
extern "C" void kernel_launch(void* const* d_in, const int* in_sizes, int n_in,
                              void* d_out, int out_size)
{
    const float* x  = (const float*)d_in[0];
    const float* wq = (const float*)d_in[1];
    const float* wk = (const float*)d_in[2];
    const float* wv = (const float*)d_in[3];
    const float* wo = (const float*)d_in[4];
    const int*   tp = (const int*)d_in[5];
    float* out = (float*)d_out;

    float *q, *k, *v, *attn;
    cudaGetSymbolAddress((void**)&q, g_q);
    cudaGetSymbolAddress((void**)&k, g_k);
    cudaGetSymbolAddress((void**)&v, g_v);
    cudaGetSymbolAddress((void**)&attn, g_attn);

    const int flash_smem = (64 * 68 * 2 + 64 * 64) * (int)sizeof(float);  // 51200
    cudaFuncSetAttribute(flash_kernel, cudaFuncAttributeMaxDynamicSharedMemorySize,
                         flash_smem);

    dim3 pgrid(8, 32);   // N/128, M/128
    proj_kernel<1><<<pgrid, 256>>>(x, wq, tp, q);
    proj_kernel<1><<<pgrid, 256>>>(x, wk, tp, k);
    proj_kernel<2><<<pgrid, 256>>>(x, wv, tp, v);
    flash_kernel<<<dim3(32, 32), 256, flash_smem>>>(q, k, v, attn);
    proj_kernel<0><<<pgrid, 256>>>(attn, wo, nullptr, out);
}

// round 2
// speedup vs baseline: 1.5173x; 1.5173x over previous
#include <cuda_runtime.h>
#include <math.h>
#include <stdint.h>

#define D_MODEL 1024
#define NHEADS  16
#define DKV     64
#define SEQL    2048
#define BATCH   2

// Scratch (allocation-free rule: __device__ globals)
__device__ float g_q[BATCH*NHEADS*SEQL*DKV];     // [b,h,s,d]
__device__ float g_k[BATCH*NHEADS*SEQL*DKV];
__device__ float g_v[BATCH*NHEADS*SEQL*DKV];
__device__ float g_attn[BATCH*SEQL*D_MODEL];     // [b,s,h*64+d]

// ---------------------------------------------------------------------------
// tf32 helpers
// ---------------------------------------------------------------------------
__device__ __forceinline__ uint32_t f2tf(float f) {
    uint32_t r;
    asm("cvt.rna.tf32.f32 %0, %1;" : "=r"(r) : "f"(f));
    return r;
}

__device__ __forceinline__ void mma8(float* c, const uint32_t* a, const uint32_t* b) {
    asm volatile(
        "mma.sync.aligned.m16n8k8.row.col.f32.tf32.tf32.f32 "
        "{%0,%1,%2,%3}, {%4,%5,%6,%7}, {%8,%9}, {%0,%1,%2,%3};"
        : "+f"(c[0]), "+f"(c[1]), "+f"(c[2]), "+f"(c[3])
        : "r"(a[0]), "r"(a[1]), "r"(a[2]), "r"(a[3]), "r"(b[0]), "r"(b[1]));
}

// ---------------------------------------------------------------------------
// Projection GEMM on tensor cores (tf32): C[m,n] = sum_k A[m,k] * W[n,k]
//   M=4096, N=1024, K=1024. Block 128x128, BK=16, 256 thr (8 warps).
//   Warp tile 32(M)x64(N) = 2 x 8 m16n8k8 fragments. Double-buffered smem.
// MODE 0: plain store out[m*1024+n]          (output projection)
// MODE 1: head layout [b,h,s,d] + RoPE       (Q, K)
// MODE 2: head layout [b,h,s,d], no RoPE     (V)
// ---------------------------------------------------------------------------
#define LDA 20   // smem row stride in words (conflict-free, 16B-aligned rows)

template<int MODE>
__global__ __launch_bounds__(256)
void proj_mma(const float* __restrict__ A, const float* __restrict__ W,
              const int* __restrict__ tpos, float* __restrict__ out)
{
    __shared__ uint32_t As[2][128 * LDA];
    __shared__ uint32_t Bs[2][128 * LDA];

    const int tid   = threadIdx.x;
    const int lane  = tid & 31;
    const int wid   = tid >> 5;
    const int warpM = wid >> 1;     // 0..3
    const int warpN = wid & 1;      // 0..1
    const int gr    = lane >> 2;    // 0..7
    const int tg    = lane & 3;     // 0..3
    const int m0    = blockIdx.y * 128;
    const int n0    = blockIdx.x * 128;

    // global->smem mapping: each thread owns 2 consecutive float4 of one row
    const int lrow = tid >> 1;            // 0..127
    const int lc4  = (tid & 1) * 2;       // float4 index 0/2 -> cols lc4*4

    const float* aptr = A + (size_t)(m0 + lrow) * 1024 + lc4 * 4;
    const float* bptr = W + (size_t)(n0 + lrow) * 1024 + lc4 * 4;

    float c[2][8][4];
#pragma unroll
    for (int mt = 0; mt < 2; mt++)
#pragma unroll
        for (int nt = 0; nt < 8; nt++)
#pragma unroll
            for (int i = 0; i < 4; i++) c[mt][nt][i] = 0.0f;

    // preload tile 0 into buffer 0
    {
        float4 a0 = *(const float4*)(aptr);
        float4 a1 = *(const float4*)(aptr + 4);
        float4 b0 = *(const float4*)(bptr);
        float4 b1 = *(const float4*)(bptr + 4);
        uint32_t* as = &As[0][lrow * LDA + lc4 * 4];
        as[0] = f2tf(a0.x); as[1] = f2tf(a0.y); as[2] = f2tf(a0.z); as[3] = f2tf(a0.w);
        as[4] = f2tf(a1.x); as[5] = f2tf(a1.y); as[6] = f2tf(a1.z); as[7] = f2tf(a1.w);
        uint32_t* bs = &Bs[0][lrow * LDA + lc4 * 4];
        bs[0] = f2tf(b0.x); bs[1] = f2tf(b0.y); bs[2] = f2tf(b0.z); bs[3] = f2tf(b0.w);
        bs[4] = f2tf(b1.x); bs[5] = f2tf(b1.y); bs[6] = f2tf(b1.z); bs[7] = f2tf(b1.w);
    }
    __syncthreads();

    for (int kt = 0; kt < 64; kt++) {
        const int cur = kt & 1;

        // prefetch next tile into registers (overlaps with compute)
        float4 pa0, pa1, pb0, pb1;
        if (kt < 63) {
            const float* ap = aptr + (kt + 1) * 16;
            pa0 = *(const float4*)(ap);
            pa1 = *(const float4*)(ap + 4);
            const float* bp = bptr + (kt + 1) * 16;
            pb0 = *(const float4*)(bp);
            pb1 = *(const float4*)(bp + 4);
        }

        // compute on current buffer: 2 k8 steps
        const uint32_t* as = As[cur];
        const uint32_t* bs = Bs[cur];
#pragma unroll
        for (int k8 = 0; k8 < 2; k8++) {
            const int kc = k8 * 8 + tg;
            uint32_t af[2][4];
#pragma unroll
            for (int mt = 0; mt < 2; mt++) {
                const int rb = warpM * 32 + mt * 16 + gr;
                af[mt][0] = as[rb * LDA + kc];
                af[mt][1] = as[(rb + 8) * LDA + kc];
                af[mt][2] = as[rb * LDA + kc + 4];
                af[mt][3] = as[(rb + 8) * LDA + kc + 4];
            }
            uint32_t bf[8][2];
#pragma unroll
            for (int nt = 0; nt < 8; nt++) {
                const int nb = warpN * 64 + nt * 8 + gr;
                bf[nt][0] = bs[nb * LDA + kc];
                bf[nt][1] = bs[nb * LDA + kc + 4];
            }
#pragma unroll
            for (int mt = 0; mt < 2; mt++)
#pragma unroll
                for (int nt = 0; nt < 8; nt++)
                    mma8(c[mt][nt], af[mt], bf[nt]);
        }

        // store prefetched tile into other buffer
        if (kt < 63) {
            uint32_t* asd = &As[1 - cur][lrow * LDA + lc4 * 4];
            asd[0] = f2tf(pa0.x); asd[1] = f2tf(pa0.y); asd[2] = f2tf(pa0.z); asd[3] = f2tf(pa0.w);
            asd[4] = f2tf(pa1.x); asd[5] = f2tf(pa1.y); asd[6] = f2tf(pa1.z); asd[7] = f2tf(pa1.w);
            uint32_t* bsd = &Bs[1 - cur][lrow * LDA + lc4 * 4];
            bsd[0] = f2tf(pb0.x); bsd[1] = f2tf(pb0.y); bsd[2] = f2tf(pb0.z); bsd[3] = f2tf(pb0.w);
            bsd[4] = f2tf(pb1.x); bsd[5] = f2tf(pb1.y); bsd[6] = f2tf(pb1.z); bsd[7] = f2tf(pb1.w);
        }
        __syncthreads();
    }

    // ---------------- epilogue ----------------
#pragma unroll
    for (int mt = 0; mt < 2; mt++) {
        const int row0 = m0 + warpM * 32 + mt * 16 + gr;
#pragma unroll
        for (int half = 0; half < 2; half++) {
            const int row = row0 + half * 8;
            const int b = row >> 11;          // /2048
            const int s = row & 2047;
            float p = 0.0f;
            if (MODE == 1) p = (float)tpos[s];
#pragma unroll
            for (int nt = 0; nt < 8; nt++) {
                float v0 = c[mt][nt][half * 2 + 0];
                float v1 = c[mt][nt][half * 2 + 1];
                const int col = n0 + warpN * 64 + nt * 8 + tg * 2;   // even
                if (MODE == 0) {
                    out[(size_t)row * 1024 + col]     = v0;
                    out[(size_t)row * 1024 + col + 1] = v1;
                } else {
                    const int h  = col >> 6;
                    const int dd = col & 63;
                    if (MODE == 1) {
                        const int jj = dd >> 1;
                        float freq = 1.0f / powf(10000.0f, (float)(2 * jj) * (1.0f / 64.0f));
                        float sn, cs;
                        sincosf(p * freq, &sn, &cs);
                        float r0 = v0 * cs - v1 * sn;
                        float r1 = v1 * cs + v0 * sn;
                        v0 = r0; v1 = r1;
                    }
                    const int dst = ((b * NHEADS + h) * SEQL + s) * DKV + dd;
                    out[dst]     = v0;
                    out[dst + 1] = v1;
                }
            }
        }
    }
}

// ---------------------------------------------------------------------------
// Flash attention, fp32, causal — UNCHANGED from R1 (known correct).
// ---------------------------------------------------------------------------
__global__ __launch_bounds__(256)
void flash_kernel(const float* __restrict__ Q, const float* __restrict__ K,
                  const float* __restrict__ V, float* __restrict__ out)
{
    extern __shared__ float sm[];
    float* Qs = sm;                 // 64*68
    float* KP = sm + 64 * 68;       // 64*68
    float* Vs = KP + 64 * 68;       // 64*64
#define QS(d, r) Qs[(d) * 68 + (r)]
#define KPS(d, r) KP[(d) * 68 + (r)]
#define VS(r, d) Vs[(r) * 64 + (d)]

    const int tid = threadIdx.x;
    const int tx  = tid & 15;
    const int ty  = tid >> 4;
    const int qt  = blockIdx.x;           // 0..31
    const int bh  = blockIdx.y;           // 0..31
    const int b   = bh >> 4;
    const int h   = bh & 15;
    const size_t base = (size_t)bh * SEQL * DKV;
    const int q0  = qt * 64;

    for (int i = tid; i < 4096; i += 256) {
        int r = i >> 6, d = i & 63;
        QS(d, r) = Q[base + (size_t)(q0 + r) * 64 + d];
    }

    float m_i[4], l_i[4], o[4][4];
#pragma unroll
    for (int i = 0; i < 4; i++) {
        m_i[i] = -1e30f; l_i[i] = 0.0f;
#pragma unroll
        for (int j = 0; j < 4; j++) o[i][j] = 0.0f;
    }

    const float scale = 0.125f;

    for (int jt = 0; jt <= qt; jt++) {
        __syncthreads();
        for (int i = tid; i < 4096; i += 256) {
            int r = i >> 6, d = i & 63;
            float kv = K[base + (size_t)(jt * 64 + r) * 64 + d];
            float vv = V[base + (size_t)(jt * 64 + r) * 64 + d];
            KPS(d, r) = kv;
            VS(r, d)  = vv;
        }
        __syncthreads();

        float s[4][4];
#pragma unroll
        for (int i = 0; i < 4; i++)
#pragma unroll
            for (int j = 0; j < 4; j++) s[i][j] = 0.0f;
#pragma unroll 8
        for (int d = 0; d < 64; d++) {
            float4 a = *(const float4*)&QS(d, ty * 4);
            float4 bb = *(const float4*)&KPS(d, tx * 4);
            float av[4] = {a.x, a.y, a.z, a.w};
            float bv[4] = {bb.x, bb.y, bb.z, bb.w};
#pragma unroll
            for (int i = 0; i < 4; i++)
#pragma unroll
                for (int j = 0; j < 4; j++)
                    s[i][j] = fmaf(av[i], bv[j], s[i][j]);
        }

        if (jt == qt) {
#pragma unroll
            for (int i = 0; i < 4; i++) {
                int qr = ty * 4 + i;
#pragma unroll
                for (int j = 0; j < 4; j++) {
                    int kc = tx * 4 + j;
                    s[i][j] = (kc > qr) ? -1e30f : s[i][j] * scale;
                }
            }
        } else {
#pragma unroll
            for (int i = 0; i < 4; i++)
#pragma unroll
                for (int j = 0; j < 4; j++) s[i][j] *= scale;
        }

        float p[4][4];
        float alpha[4];
#pragma unroll
        for (int i = 0; i < 4; i++) {
            float mx = fmaxf(fmaxf(s[i][0], s[i][1]), fmaxf(s[i][2], s[i][3]));
            mx = fmaxf(mx, __shfl_xor_sync(0xffffffffu, mx, 1));
            mx = fmaxf(mx, __shfl_xor_sync(0xffffffffu, mx, 2));
            mx = fmaxf(mx, __shfl_xor_sync(0xffffffffu, mx, 4));
            mx = fmaxf(mx, __shfl_xor_sync(0xffffffffu, mx, 8));
            float mn = fmaxf(m_i[i], mx);
            alpha[i] = __expf(m_i[i] - mn);
            m_i[i] = mn;
            float rs = 0.0f;
#pragma unroll
            for (int j = 0; j < 4; j++) {
                p[i][j] = __expf(s[i][j] - mn);
                rs += p[i][j];
            }
            rs += __shfl_xor_sync(0xffffffffu, rs, 1);
            rs += __shfl_xor_sync(0xffffffffu, rs, 2);
            rs += __shfl_xor_sync(0xffffffffu, rs, 4);
            rs += __shfl_xor_sync(0xffffffffu, rs, 8);
            l_i[i] = l_i[i] * alpha[i] + rs;
#pragma unroll
            for (int j = 0; j < 4; j++) o[i][j] *= alpha[i];
        }

        __syncthreads();
#pragma unroll
        for (int i = 0; i < 4; i++)
#pragma unroll
            for (int j = 0; j < 4; j++)
                KPS(tx * 4 + j, ty * 4 + i) = p[i][j];
        __syncthreads();

#pragma unroll 8
        for (int kc = 0; kc < 64; kc++) {
            float4 a = *(const float4*)&KPS(kc, ty * 4);
            float4 bb = *(const float4*)&VS(kc, tx * 4);
            float av[4] = {a.x, a.y, a.z, a.w};
            float bv[4] = {bb.x, bb.y, bb.z, bb.w};
#pragma unroll
            for (int i = 0; i < 4; i++)
#pragma unroll
                for (int j = 0; j < 4; j++)
                    o[i][j] = fmaf(av[i], bv[j], o[i][j]);
        }
    }

#pragma unroll
    for (int i = 0; i < 4; i++) {
        float inv = 1.0f / l_i[i];
        int srow = q0 + ty * 4 + i;
        size_t ob = (size_t)(b * SEQL + srow) * 1024 + h * 64;
#pragma unroll
        for (int j = 0; j < 4; j++)
            out[ob + tx * 4 + j] = o[i][j] * inv;
    }
#undef QS
#undef KPS
#undef VS
}

// ---------------------------------------------------------------------------
extern "C" void kernel_launch(void* const* d_in, const int* in_sizes, int n_in,
                              void* d_out, int out_size)
{
    const float* x  = (const float*)d_in[0];
    const float* wq = (const float*)d_in[1];
    const float* wk = (const float*)d_in[2];
    const float* wv = (const float*)d_in[3];
    const float* wo = (const float*)d_in[4];
    const int*   tp = (const int*)d_in[5];
    float* out = (float*)d_out;

    float *q, *k, *v, *attn;
    cudaGetSymbolAddress((void**)&q, g_q);
    cudaGetSymbolAddress((void**)&k, g_k);
    cudaGetSymbolAddress((void**)&v, g_v);
    cudaGetSymbolAddress((void**)&attn, g_attn);

    const int flash_smem = (64 * 68 * 2 + 64 * 64) * (int)sizeof(float);  // 51200
    cudaFuncSetAttribute(flash_kernel, cudaFuncAttributeMaxDynamicSharedMemorySize,
                         flash_smem);

    dim3 pgrid(8, 32);   // N/128, M/128
    proj_mma<1><<<pgrid, 256>>>(x, wq, tp, q);
    proj_mma<1><<<pgrid, 256>>>(x, wk, tp, k);
    proj_mma<2><<<pgrid, 256>>>(x, wv, tp, v);
    flash_kernel<<<dim3(32, 32), 256, flash_smem>>>(q, k, v, attn);
    proj_mma<0><<<pgrid, 256>>>(attn, wo, nullptr, out);
}

// round 4
// speedup vs baseline: 2.4153x; 1.5918x over previous
#include <cuda_runtime.h>
#include <math.h>
#include <stdint.h>

#define D_MODEL 1024
#define NHEADS  16
#define DKV     64
#define SEQL    2048
#define BATCH   2

// Scratch (allocation-free rule: __device__ globals)
__device__ float g_q[BATCH*NHEADS*SEQL*DKV];     // [b,h,s,d]
__device__ float g_k[BATCH*NHEADS*SEQL*DKV];
__device__ float g_v[BATCH*NHEADS*SEQL*DKV];
__device__ float g_attn[BATCH*SEQL*D_MODEL];     // [b,s,h*64+d]

// ---------------------------------------------------------------------------
// tf32 helpers
// ---------------------------------------------------------------------------
__device__ __forceinline__ uint32_t f2tf(float f) {
    uint32_t r;
    asm("cvt.rna.tf32.f32 %0, %1;" : "=r"(r) : "f"(f));
    return r;
}

__device__ __forceinline__ void mma8(float* c, const uint32_t* a, const uint32_t* b) {
    asm volatile(
        "mma.sync.aligned.m16n8k8.row.col.f32.tf32.tf32.f32 "
        "{%0,%1,%2,%3}, {%4,%5,%6,%7}, {%8,%9}, {%0,%1,%2,%3};"
        : "+f"(c[0]), "+f"(c[1]), "+f"(c[2]), "+f"(c[3])
        : "r"(a[0]), "r"(a[1]), "r"(a[2]), "r"(a[3]), "r"(b[0]), "r"(b[1]));
}

// ---------------------------------------------------------------------------
// Projection GEMM on tensor cores (tf32) — UNCHANGED from R2.
// ---------------------------------------------------------------------------
#define LDA 20

template<int MODE>
__global__ __launch_bounds__(256)
void proj_mma(const float* __restrict__ A, const float* __restrict__ W,
              const int* __restrict__ tpos, float* __restrict__ out)
{
    __shared__ uint32_t As[2][128 * LDA];
    __shared__ uint32_t Bs[2][128 * LDA];

    const int tid   = threadIdx.x;
    const int lane  = tid & 31;
    const int wid   = tid >> 5;
    const int warpM = wid >> 1;
    const int warpN = wid & 1;
    const int gr    = lane >> 2;
    const int tg    = lane & 3;
    const int m0    = blockIdx.y * 128;
    const int n0    = blockIdx.x * 128;

    const int lrow = tid >> 1;
    const int lc4  = (tid & 1) * 2;

    const float* aptr = A + (size_t)(m0 + lrow) * 1024 + lc4 * 4;
    const float* bptr = W + (size_t)(n0 + lrow) * 1024 + lc4 * 4;

    float c[2][8][4];
#pragma unroll
    for (int mt = 0; mt < 2; mt++)
#pragma unroll
        for (int nt = 0; nt < 8; nt++)
#pragma unroll
            for (int i = 0; i < 4; i++) c[mt][nt][i] = 0.0f;

    {
        float4 a0 = *(const float4*)(aptr);
        float4 a1 = *(const float4*)(aptr + 4);
        float4 b0 = *(const float4*)(bptr);
        float4 b1 = *(const float4*)(bptr + 4);
        uint32_t* as = &As[0][lrow * LDA + lc4 * 4];
        as[0] = f2tf(a0.x); as[1] = f2tf(a0.y); as[2] = f2tf(a0.z); as[3] = f2tf(a0.w);
        as[4] = f2tf(a1.x); as[5] = f2tf(a1.y); as[6] = f2tf(a1.z); as[7] = f2tf(a1.w);
        uint32_t* bs = &Bs[0][lrow * LDA + lc4 * 4];
        bs[0] = f2tf(b0.x); bs[1] = f2tf(b0.y); bs[2] = f2tf(b0.z); bs[3] = f2tf(b0.w);
        bs[4] = f2tf(b1.x); bs[5] = f2tf(b1.y); bs[6] = f2tf(b1.z); bs[7] = f2tf(b1.w);
    }
    __syncthreads();

    for (int kt = 0; kt < 64; kt++) {
        const int cur = kt & 1;

        float4 pa0, pa1, pb0, pb1;
        if (kt < 63) {
            const float* ap = aptr + (kt + 1) * 16;
            pa0 = *(const float4*)(ap);
            pa1 = *(const float4*)(ap + 4);
            const float* bp = bptr + (kt + 1) * 16;
            pb0 = *(const float4*)(bp);
            pb1 = *(const float4*)(bp + 4);
        }

        const uint32_t* as = As[cur];
        const uint32_t* bs = Bs[cur];
#pragma unroll
        for (int k8 = 0; k8 < 2; k8++) {
            const int kc = k8 * 8 + tg;
            uint32_t af[2][4];
#pragma unroll
            for (int mt = 0; mt < 2; mt++) {
                const int rb = warpM * 32 + mt * 16 + gr;
                af[mt][0] = as[rb * LDA + kc];
                af[mt][1] = as[(rb + 8) * LDA + kc];
                af[mt][2] = as[rb * LDA + kc + 4];
                af[mt][3] = as[(rb + 8) * LDA + kc + 4];
            }
            uint32_t bf[8][2];
#pragma unroll
            for (int nt = 0; nt < 8; nt++) {
                const int nb = warpN * 64 + nt * 8 + gr;
                bf[nt][0] = bs[nb * LDA + kc];
                bf[nt][1] = bs[nb * LDA + kc + 4];
            }
#pragma unroll
            for (int mt = 0; mt < 2; mt++)
#pragma unroll
                for (int nt = 0; nt < 8; nt++)
                    mma8(c[mt][nt], af[mt], bf[nt]);
        }

        if (kt < 63) {
            uint32_t* asd = &As[1 - cur][lrow * LDA + lc4 * 4];
            asd[0] = f2tf(pa0.x); asd[1] = f2tf(pa0.y); asd[2] = f2tf(pa0.z); asd[3] = f2tf(pa0.w);
            asd[4] = f2tf(pa1.x); asd[5] = f2tf(pa1.y); asd[6] = f2tf(pa1.z); asd[7] = f2tf(pa1.w);
            uint32_t* bsd = &Bs[1 - cur][lrow * LDA + lc4 * 4];
            bsd[0] = f2tf(pb0.x); bsd[1] = f2tf(pb0.y); bsd[2] = f2tf(pb0.z); bsd[3] = f2tf(pb0.w);
            bsd[4] = f2tf(pb1.x); bsd[5] = f2tf(pb1.y); bsd[6] = f2tf(pb1.z); bsd[7] = f2tf(pb1.w);
        }
        __syncthreads();
    }

#pragma unroll
    for (int mt = 0; mt < 2; mt++) {
        const int row0 = m0 + warpM * 32 + mt * 16 + gr;
#pragma unroll
        for (int half = 0; half < 2; half++) {
            const int row = row0 + half * 8;
            const int b = row >> 11;
            const int s = row & 2047;
            float p = 0.0f;
            if (MODE == 1) p = (float)tpos[s];
#pragma unroll
            for (int nt = 0; nt < 8; nt++) {
                float v0 = c[mt][nt][half * 2 + 0];
                float v1 = c[mt][nt][half * 2 + 1];
                const int col = n0 + warpN * 64 + nt * 8 + tg * 2;
                if (MODE == 0) {
                    out[(size_t)row * 1024 + col]     = v0;
                    out[(size_t)row * 1024 + col + 1] = v1;
                } else {
                    const int h  = col >> 6;
                    const int dd = col & 63;
                    if (MODE == 1) {
                        const int jj = dd >> 1;
                        float freq = 1.0f / powf(10000.0f, (float)(2 * jj) * (1.0f / 64.0f));
                        float sn, cs;
                        sincosf(p * freq, &sn, &cs);
                        float r0 = v0 * cs - v1 * sn;
                        float r1 = v1 * cs + v0 * sn;
                        v0 = r0; v1 = r1;
                    }
                    const int dst = ((b * NHEADS + h) * SEQL + s) * DKV + dd;
                    out[dst]     = v0;
                    out[dst + 1] = v1;
                }
            }
        }
    }
}

// ---------------------------------------------------------------------------
// Flash attention v2: tensor-core tf32 QK^T and PV.
//   Grid (32 qtiles, 32 bh). Block 128 thr = 4 warps. 64 q-rows per block,
//   warp w owns rows [16w, 16w+16). Online softmax in registers; P staged in
//   warp-private smem (syncwarp only).
// smem strides (bank-conflict-free for the fragment patterns):
//   Qs/Ks/Ps stride 68 (A / row-pattern: 4*gr+tg distinct)
//   Vs stride 72       (B col-pattern: 8*tg+gr distinct)
// ---------------------------------------------------------------------------
#define QKS 68
#define VST 72

__global__ __launch_bounds__(128)
void flash_mma(const float* __restrict__ Q, const float* __restrict__ K,
               const float* __restrict__ V, float* __restrict__ out)
{
    extern __shared__ uint32_t sm[];
    uint32_t* Qs = sm;                       // 64*68
    uint32_t* Ks = Qs + 64 * QKS;            // 64*68
    uint32_t* Vs = Ks + 64 * QKS;            // 64*72
    uint32_t* Ps = Vs + 64 * VST;            // 4 * 16*68

    const int tid  = threadIdx.x;
    const int lane = tid & 31;
    const int wid  = tid >> 5;
    const int gr   = lane >> 2;    // 0..7
    const int tg   = lane & 3;     // 0..3
    const int qt   = blockIdx.x;
    const int bh   = blockIdx.y;
    const int b    = bh >> 4;
    const int h    = bh & 15;
    const size_t base = (size_t)bh * SEQL * DKV;
    const int q0   = qt * 64;
    const int rb   = wid * 16;               // warp's q-row base in tile
    uint32_t* Pw   = Ps + wid * 16 * QKS;    // warp-private P

    // Load Q tile (tf32): 64 rows x 64 cols
    for (int i = tid; i < 1024; i += 128) {
        const int r = i >> 4, c4 = (i & 15) * 4;
        float4 q4 = *(const float4*)&Q[base + (size_t)(q0 + r) * 64 + c4];
        uint32_t* d = &Qs[r * QKS + c4];
        d[0] = f2tf(q4.x); d[1] = f2tf(q4.y); d[2] = f2tf(q4.z); d[3] = f2tf(q4.w);
    }

    float o[8][4];
#pragma unroll
    for (int nf = 0; nf < 8; nf++)
#pragma unroll
        for (int i = 0; i < 4; i++) o[nf][i] = 0.0f;
    float m_i[2] = {-1e30f, -1e30f};
    float l_i[2] = {0.0f, 0.0f};

    for (int jt = 0; jt <= qt; jt++) {
        __syncthreads();   // previous iter's reads of Ks/Vs done (and Q store iter0)
        for (int i = tid; i < 1024; i += 128) {
            const int r = i >> 4, c4 = (i & 15) * 4;
            const size_t g = base + (size_t)(jt * 64 + r) * 64 + c4;
            float4 k4 = *(const float4*)&K[g];
            float4 v4 = *(const float4*)&V[g];
            uint32_t* dk = &Ks[r * QKS + c4];
            dk[0] = f2tf(k4.x); dk[1] = f2tf(k4.y); dk[2] = f2tf(k4.z); dk[3] = f2tf(k4.w);
            uint32_t* dv = &Vs[r * VST + c4];
            dv[0] = f2tf(v4.x); dv[1] = f2tf(v4.y); dv[2] = f2tf(v4.z); dv[3] = f2tf(v4.w);
        }
        __syncthreads();

        // ---- S = Q K^T : warp rows [rb, rb+16), all 64 kv cols ----
        float s[8][4];
#pragma unroll
        for (int nf = 0; nf < 8; nf++)
#pragma unroll
            for (int i = 0; i < 4; i++) s[nf][i] = 0.0f;

#pragma unroll
        for (int ks = 0; ks < 8; ks++) {
            const int kc = ks * 8 + tg;
            uint32_t a[4];
            a[0] = Qs[(rb + gr) * QKS + kc];
            a[1] = Qs[(rb + gr + 8) * QKS + kc];
            a[2] = Qs[(rb + gr) * QKS + kc + 4];
            a[3] = Qs[(rb + gr + 8) * QKS + kc + 4];
#pragma unroll
            for (int nf = 0; nf < 8; nf++) {
                uint32_t bf[2];
                bf[0] = Ks[(nf * 8 + gr) * QKS + kc];
                bf[1] = Ks[(nf * 8 + gr) * QKS + kc + 4];
                mma8(s[nf], a, bf);
            }
        }

        // ---- scale + causal mask ----
        const float scale = 0.125f;
        if (jt == qt) {
#pragma unroll
            for (int nf = 0; nf < 8; nf++) {
                const int col = nf * 8 + tg * 2;
#pragma unroll
                for (int hf = 0; hf < 2; hf++) {
                    const int row = rb + gr + 8 * hf;
                    s[nf][2*hf]   = (col     > row) ? -1e30f : s[nf][2*hf]   * scale;
                    s[nf][2*hf+1] = (col + 1 > row) ? -1e30f : s[nf][2*hf+1] * scale;
                }
            }
        } else {
#pragma unroll
            for (int nf = 0; nf < 8; nf++)
#pragma unroll
                for (int i = 0; i < 4; i++) s[nf][i] *= scale;
        }

        // ---- online softmax (row owned by 4 lanes: same gr, tg=0..3) ----
        float p[8][4];
#pragma unroll
        for (int hf = 0; hf < 2; hf++) {
            float mx = -1e30f;
#pragma unroll
            for (int nf = 0; nf < 8; nf++)
                mx = fmaxf(mx, fmaxf(s[nf][2*hf], s[nf][2*hf+1]));
            mx = fmaxf(mx, __shfl_xor_sync(0xffffffffu, mx, 1));
            mx = fmaxf(mx, __shfl_xor_sync(0xffffffffu, mx, 2));
            const float mn = fmaxf(m_i[hf], mx);
            const float alpha = __expf(m_i[hf] - mn);
            m_i[hf] = mn;
            float rs = 0.0f;
#pragma unroll
            for (int nf = 0; nf < 8; nf++) {
                float p0 = __expf(s[nf][2*hf]   - mn);
                float p1 = __expf(s[nf][2*hf+1] - mn);
                p[nf][2*hf] = p0; p[nf][2*hf+1] = p1;
                rs += p0 + p1;
            }
            rs += __shfl_xor_sync(0xffffffffu, rs, 1);
            rs += __shfl_xor_sync(0xffffffffu, rs, 2);
            l_i[hf] = l_i[hf] * alpha + rs;
#pragma unroll
            for (int nf = 0; nf < 8; nf++) {
                o[nf][2*hf]   *= alpha;
                o[nf][2*hf+1] *= alpha;
            }
        }

        // ---- stage P in warp-private smem (tf32) ----
#pragma unroll
        for (int nf = 0; nf < 8; nf++) {
            const int col = nf * 8 + tg * 2;
            Pw[gr * QKS + col]           = f2tf(p[nf][0]);
            Pw[gr * QKS + col + 1]       = f2tf(p[nf][1]);
            Pw[(gr + 8) * QKS + col]     = f2tf(p[nf][2]);
            Pw[(gr + 8) * QKS + col + 1] = f2tf(p[nf][3]);
        }
        __syncwarp();

        // ---- O += P V ----
#pragma unroll
        for (int ks = 0; ks < 8; ks++) {
            const int kc = ks * 8 + tg;
            uint32_t a[4];
            a[0] = Pw[gr * QKS + kc];
            a[1] = Pw[(gr + 8) * QKS + kc];
            a[2] = Pw[gr * QKS + kc + 4];
            a[3] = Pw[(gr + 8) * QKS + kc + 4];
#pragma unroll
            for (int nf = 0; nf < 8; nf++) {
                uint32_t bf[2];
                bf[0] = Vs[(ks * 8 + tg) * VST + nf * 8 + gr];
                bf[1] = Vs[(ks * 8 + tg + 4) * VST + nf * 8 + gr];
                mma8(o[nf], a, bf);
            }
        }
        __syncwarp();   // P reads done before next iter overwrites
    }

    // ---- normalize + store [b, s, h*64 + d] ----
#pragma unroll
    for (int hf = 0; hf < 2; hf++) {
        const float inv = 1.0f / l_i[hf];
        const int srow = q0 + rb + gr + 8 * hf;
        const size_t ob = (size_t)(b * SEQL + srow) * 1024 + h * 64;
#pragma unroll
        for (int nf = 0; nf < 8; nf++) {
            const int col = nf * 8 + tg * 2;
            float2 v2 = make_float2(o[nf][2*hf] * inv, o[nf][2*hf+1] * inv);
            *(float2*)&out[ob + col] = v2;
        }
    }
}

// ---------------------------------------------------------------------------
extern "C" void kernel_launch(void* const* d_in, const int* in_sizes, int n_in,
                              void* d_out, int out_size)
{
    const float* x  = (const float*)d_in[0];
    const float* wq = (const float*)d_in[1];
    const float* wk = (const float*)d_in[2];
    const float* wv = (const float*)d_in[3];
    const float* wo = (const float*)d_in[4];
    const int*   tp = (const int*)d_in[5];
    float* out = (float*)d_out;

    float *q, *k, *v, *attn;
    cudaGetSymbolAddress((void**)&q, g_q);
    cudaGetSymbolAddress((void**)&k, g_k);
    cudaGetSymbolAddress((void**)&v, g_v);
    cudaGetSymbolAddress((void**)&attn, g_attn);

    // Qs + Ks (64*68) + Vs (64*72) + Ps (4*16*68), u32 words
    const int flash_smem = (64*QKS*2 + 64*VST + 4*16*QKS) * (int)sizeof(uint32_t); // 70656
    cudaFuncSetAttribute(flash_mma, cudaFuncAttributeMaxDynamicSharedMemorySize,
                         flash_smem);

    dim3 pgrid(8, 32);   // N/128, M/128
    proj_mma<1><<<pgrid, 256>>>(x, wq, tp, q);
    proj_mma<1><<<pgrid, 256>>>(x, wk, tp, k);
    proj_mma<2><<<pgrid, 256>>>(x, wv, tp, v);
    flash_mma<<<dim3(32, 32), 128, flash_smem>>>(q, k, v, attn);
    proj_mma<0><<<pgrid, 256>>>(attn, wo, nullptr, out);
}

// round 6
// speedup vs baseline: 2.4310x; 1.0065x over previous
#include <cuda_runtime.h>
#include <math.h>
#include <stdint.h>

#define D_MODEL 1024
#define NHEADS  16
#define DKV     64
#define SEQL    2048
#define BATCH   2

// Scratch (allocation-free rule: __device__ globals)
__device__ float g_q[BATCH*NHEADS*SEQL*DKV];     // [b,h,s,d]
__device__ float g_k[BATCH*NHEADS*SEQL*DKV];
__device__ float g_v[BATCH*NHEADS*SEQL*DKV];
__device__ float g_attn[BATCH*SEQL*D_MODEL];     // [b,s,h*64+d]

// ---------------------------------------------------------------------------
// tf32 helpers
// ---------------------------------------------------------------------------
__device__ __forceinline__ uint32_t f2tf(float f) {
    uint32_t r;
    asm("cvt.rna.tf32.f32 %0, %1;" : "=r"(r) : "f"(f));
    return r;
}

__device__ __forceinline__ void mma8(float* c, const uint32_t* a, const uint32_t* b) {
    asm volatile(
        "mma.sync.aligned.m16n8k8.row.col.f32.tf32.tf32.f32 "
        "{%0,%1,%2,%3}, {%4,%5,%6,%7}, {%8,%9}, {%0,%1,%2,%3};"
        : "+f"(c[0]), "+f"(c[1]), "+f"(c[2]), "+f"(c[3])
        : "r"(a[0]), "r"(a[1]), "r"(a[2]), "r"(a[3]), "r"(b[0]), "r"(b[1]));
}

// ---------------------------------------------------------------------------
// Projection GEMM on tensor cores (tf32) — UNCHANGED (known correct).
// ---------------------------------------------------------------------------
#define LDA 20

template<int MODE>
__global__ __launch_bounds__(256)
void proj_mma(const float* __restrict__ A, const float* __restrict__ W,
              const int* __restrict__ tpos, float* __restrict__ out)
{
    __shared__ uint32_t As[2][128 * LDA];
    __shared__ uint32_t Bs[2][128 * LDA];

    const int tid   = threadIdx.x;
    const int lane  = tid & 31;
    const int wid   = tid >> 5;
    const int warpM = wid >> 1;
    const int warpN = wid & 1;
    const int gr    = lane >> 2;
    const int tg    = lane & 3;
    const int m0    = blockIdx.y * 128;
    const int n0    = blockIdx.x * 128;

    const int lrow = tid >> 1;
    const int lc4  = (tid & 1) * 2;

    const float* aptr = A + (size_t)(m0 + lrow) * 1024 + lc4 * 4;
    const float* bptr = W + (size_t)(n0 + lrow) * 1024 + lc4 * 4;

    float c[2][8][4];
#pragma unroll
    for (int mt = 0; mt < 2; mt++)
#pragma unroll
        for (int nt = 0; nt < 8; nt++)
#pragma unroll
            for (int i = 0; i < 4; i++) c[mt][nt][i] = 0.0f;

    {
        float4 a0 = *(const float4*)(aptr);
        float4 a1 = *(const float4*)(aptr + 4);
        float4 b0 = *(const float4*)(bptr);
        float4 b1 = *(const float4*)(bptr + 4);
        uint32_t* as = &As[0][lrow * LDA + lc4 * 4];
        as[0] = f2tf(a0.x); as[1] = f2tf(a0.y); as[2] = f2tf(a0.z); as[3] = f2tf(a0.w);
        as[4] = f2tf(a1.x); as[5] = f2tf(a1.y); as[6] = f2tf(a1.z); as[7] = f2tf(a1.w);
        uint32_t* bs = &Bs[0][lrow * LDA + lc4 * 4];
        bs[0] = f2tf(b0.x); bs[1] = f2tf(b0.y); bs[2] = f2tf(b0.z); bs[3] = f2tf(b0.w);
        bs[4] = f2tf(b1.x); bs[5] = f2tf(b1.y); bs[6] = f2tf(b1.z); bs[7] = f2tf(b1.w);
    }
    __syncthreads();

    for (int kt = 0; kt < 64; kt++) {
        const int cur = kt & 1;

        float4 pa0, pa1, pb0, pb1;
        if (kt < 63) {
            const float* ap = aptr + (kt + 1) * 16;
            pa0 = *(const float4*)(ap);
            pa1 = *(const float4*)(ap + 4);
            const float* bp = bptr + (kt + 1) * 16;
            pb0 = *(const float4*)(bp);
            pb1 = *(const float4*)(bp + 4);
        }

        const uint32_t* as = As[cur];
        const uint32_t* bs = Bs[cur];
#pragma unroll
        for (int k8 = 0; k8 < 2; k8++) {
            const int kc = k8 * 8 + tg;
            uint32_t af[2][4];
#pragma unroll
            for (int mt = 0; mt < 2; mt++) {
                const int rb = warpM * 32 + mt * 16 + gr;
                af[mt][0] = as[rb * LDA + kc];
                af[mt][1] = as[(rb + 8) * LDA + kc];
                af[mt][2] = as[rb * LDA + kc + 4];
                af[mt][3] = as[(rb + 8) * LDA + kc + 4];
            }
            uint32_t bf[8][2];
#pragma unroll
            for (int nt = 0; nt < 8; nt++) {
                const int nb = warpN * 64 + nt * 8 + gr;
                bf[nt][0] = bs[nb * LDA + kc];
                bf[nt][1] = bs[nb * LDA + kc + 4];
            }
#pragma unroll
            for (int mt = 0; mt < 2; mt++)
#pragma unroll
                for (int nt = 0; nt < 8; nt++)
                    mma8(c[mt][nt], af[mt], bf[nt]);
        }

        if (kt < 63) {
            uint32_t* asd = &As[1 - cur][lrow * LDA + lc4 * 4];
            asd[0] = f2tf(pa0.x); asd[1] = f2tf(pa0.y); asd[2] = f2tf(pa0.z); asd[3] = f2tf(pa0.w);
            asd[4] = f2tf(pa1.x); asd[5] = f2tf(pa1.y); asd[6] = f2tf(pa1.z); asd[7] = f2tf(pa1.w);
            uint32_t* bsd = &Bs[1 - cur][lrow * LDA + lc4 * 4];
            bsd[0] = f2tf(pb0.x); bsd[1] = f2tf(pb0.y); bsd[2] = f2tf(pb0.z); bsd[3] = f2tf(pb0.w);
            bsd[4] = f2tf(pb1.x); bsd[5] = f2tf(pb1.y); bsd[6] = f2tf(pb1.z); bsd[7] = f2tf(pb1.w);
        }
        __syncthreads();
    }

#pragma unroll
    for (int mt = 0; mt < 2; mt++) {
        const int row0 = m0 + warpM * 32 + mt * 16 + gr;
#pragma unroll
        for (int half = 0; half < 2; half++) {
            const int row = row0 + half * 8;
            const int b = row >> 11;
            const int s = row & 2047;
            float p = 0.0f;
            if (MODE == 1) p = (float)tpos[s];
#pragma unroll
            for (int nt = 0; nt < 8; nt++) {
                float v0 = c[mt][nt][half * 2 + 0];
                float v1 = c[mt][nt][half * 2 + 1];
                const int col = n0 + warpN * 64 + nt * 8 + tg * 2;
                if (MODE == 0) {
                    out[(size_t)row * 1024 + col]     = v0;
                    out[(size_t)row * 1024 + col + 1] = v1;
                } else {
                    const int h  = col >> 6;
                    const int dd = col & 63;
                    if (MODE == 1) {
                        const int jj = dd >> 1;
                        float freq = 1.0f / powf(10000.0f, (float)(2 * jj) * (1.0f / 64.0f));
                        float sn, cs;
                        sincosf(p * freq, &sn, &cs);
                        float r0 = v0 * cs - v1 * sn;
                        float r1 = v1 * cs + v0 * sn;
                        v0 = r0; v1 = r1;
                    }
                    const int dst = ((b * NHEADS + h) * SEQL + s) * DKV + dd;
                    out[dst]     = v0;
                    out[dst + 1] = v1;
                }
            }
        }
    }
}

// ---------------------------------------------------------------------------
// Flash attention v3: tf32 mma, 128-row Q tiles, 8 warps / 256 threads.
//   Grid (16 qtiles heavy-first, 32 bh). Warp w owns q rows [16w, 16w+16).
//   KV tiles of 64 rows, jt = 0 .. 2*qt+1. Online softmax in registers;
//   P staged in warp-private smem (syncwarp only).
// smem strides: Qs/Ks/Ps stride 68, Vs stride 72 (conflict-free patterns).
// ---------------------------------------------------------------------------
#define QKS 68
#define VST 72

__global__ __launch_bounds__(256)
void flash_mma(const float* __restrict__ Q, const float* __restrict__ K,
               const float* __restrict__ V, float* __restrict__ out)
{
    extern __shared__ uint32_t sm[];
    uint32_t* Qs = sm;                       // 128*68
    uint32_t* Ks = Qs + 128 * QKS;           // 64*68
    uint32_t* Vs = Ks + 64 * QKS;            // 64*72
    uint32_t* Ps = Vs + 64 * VST;            // 8 * 16*68

    const int tid  = threadIdx.x;
    const int lane = tid & 31;
    const int wid  = tid >> 5;
    const int gr   = lane >> 2;    // 0..7
    const int tg   = lane & 3;     // 0..3
    const int qt   = 15 - blockIdx.x;        // heavy tiles first
    const int bh   = blockIdx.y;
    const int b    = bh >> 4;
    const int h    = bh & 15;
    const size_t base = (size_t)bh * SEQL * DKV;
    const int q0   = qt * 128;
    const int rb   = wid * 16;               // warp's q-row base in tile
    uint32_t* Pw   = Ps + wid * 16 * QKS;    // warp-private P

    // Load Q tile (tf32): 128 rows x 64 cols
    for (int i = tid; i < 2048; i += 256) {
        const int r = i >> 4, c4 = (i & 15) * 4;
        float4 q4 = *(const float4*)&Q[base + (size_t)(q0 + r) * 64 + c4];
        uint32_t* d = &Qs[r * QKS + c4];
        d[0] = f2tf(q4.x); d[1] = f2tf(q4.y); d[2] = f2tf(q4.z); d[3] = f2tf(q4.w);
    }

    float o[8][4];
#pragma unroll
    for (int nf = 0; nf < 8; nf++)
#pragma unroll
        for (int i = 0; i < 4; i++) o[nf][i] = 0.0f;
    float m_i[2] = {-1e30f, -1e30f};
    float l_i[2] = {0.0f, 0.0f};

    const int njt = 2 * qt + 2;
    for (int jt = 0; jt < njt; jt++) {
        __syncthreads();   // prev iter's reads of Ks/Vs done (and Q store iter0)
        for (int i = tid; i < 1024; i += 256) {
            const int r = i >> 4, c4 = (i & 15) * 4;
            const size_t g = base + (size_t)(jt * 64 + r) * 64 + c4;
            float4 k4 = *(const float4*)&K[g];
            float4 v4 = *(const float4*)&V[g];
            uint32_t* dk = &Ks[r * QKS + c4];
            dk[0] = f2tf(k4.x); dk[1] = f2tf(k4.y); dk[2] = f2tf(k4.z); dk[3] = f2tf(k4.w);
            uint32_t* dv = &Vs[r * VST + c4];
            dv[0] = f2tf(v4.x); dv[1] = f2tf(v4.y); dv[2] = f2tf(v4.z); dv[3] = f2tf(v4.w);
        }
        __syncthreads();

        // ---- S = Q K^T : warp rows [rb, rb+16), all 64 kv cols ----
        float s[8][4];
#pragma unroll
        for (int nf = 0; nf < 8; nf++)
#pragma unroll
            for (int i = 0; i < 4; i++) s[nf][i] = 0.0f;

#pragma unroll
        for (int ks = 0; ks < 8; ks++) {
            const int kc = ks * 8 + tg;
            uint32_t a[4];
            a[0] = Qs[(rb + gr) * QKS + kc];
            a[1] = Qs[(rb + gr + 8) * QKS + kc];
            a[2] = Qs[(rb + gr) * QKS + kc + 4];
            a[3] = Qs[(rb + gr + 8) * QKS + kc + 4];
#pragma unroll
            for (int nf = 0; nf < 8; nf++) {
                uint32_t bf[2];
                bf[0] = Ks[(nf * 8 + gr) * QKS + kc];
                bf[1] = Ks[(nf * 8 + gr) * QKS + kc + 4];
                mma8(s[nf], a, bf);
            }
        }

        // ---- scale + causal mask (only tiles overlapping the diagonal) ----
        const float scale = 0.125f;
        if (jt >= 2 * qt) {
#pragma unroll
            for (int nf = 0; nf < 8; nf++) {
                const int colg = jt * 64 + nf * 8 + tg * 2;
#pragma unroll
                for (int hf = 0; hf < 2; hf++) {
                    const int rowg = q0 + rb + gr + 8 * hf;
                    s[nf][2*hf]   = (colg     > rowg) ? -1e30f : s[nf][2*hf]   * scale;
                    s[nf][2*hf+1] = (colg + 1 > rowg) ? -1e30f : s[nf][2*hf+1] * scale;
                }
            }
        } else {
#pragma unroll
            for (int nf = 0; nf < 8; nf++)
#pragma unroll
                for (int i = 0; i < 4; i++) s[nf][i] *= scale;
        }

        // ---- online softmax (row owned by 4 lanes: same gr, tg=0..3) ----
        float p[8][4];
#pragma unroll
        for (int hf = 0; hf < 2; hf++) {
            float mx = -1e30f;
#pragma unroll
            for (int nf = 0; nf < 8; nf++)
                mx = fmaxf(mx, fmaxf(s[nf][2*hf], s[nf][2*hf+1]));
            mx = fmaxf(mx, __shfl_xor_sync(0xffffffffu, mx, 1));
            mx = fmaxf(mx, __shfl_xor_sync(0xffffffffu, mx, 2));
            const float mn = fmaxf(m_i[hf], mx);
            const float alpha = __expf(m_i[hf] - mn);
            m_i[hf] = mn;
            float rs = 0.0f;
#pragma unroll
            for (int nf = 0; nf < 8; nf++) {
                float p0 = __expf(s[nf][2*hf]   - mn);
                float p1 = __expf(s[nf][2*hf+1] - mn);
                p[nf][2*hf] = p0; p[nf][2*hf+1] = p1;
                rs += p0 + p1;
            }
            rs += __shfl_xor_sync(0xffffffffu, rs, 1);
            rs += __shfl_xor_sync(0xffffffffu, rs, 2);
            l_i[hf] = l_i[hf] * alpha + rs;
#pragma unroll
            for (int nf = 0; nf < 8; nf++) {
                o[nf][2*hf]   *= alpha;
                o[nf][2*hf+1] *= alpha;
            }
        }

        // ---- stage P in warp-private smem (tf32) ----
#pragma unroll
        for (int nf = 0; nf < 8; nf++) {
            const int col = nf * 8 + tg * 2;
            Pw[gr * QKS + col]           = f2tf(p[nf][0]);
            Pw[gr * QKS + col + 1]       = f2tf(p[nf][1]);
            Pw[(gr + 8) * QKS + col]     = f2tf(p[nf][2]);
            Pw[(gr + 8) * QKS + col + 1] = f2tf(p[nf][3]);
        }
        __syncwarp();

        // ---- O += P V ----
#pragma unroll
        for (int ks = 0; ks < 8; ks++) {
            const int kc = ks * 8 + tg;
            uint32_t a[4];
            a[0] = Pw[gr * QKS + kc];
            a[1] = Pw[(gr + 8) * QKS + kc];
            a[2] = Pw[gr * QKS + kc + 4];
            a[3] = Pw[(gr + 8) * QKS + kc + 4];
#pragma unroll
            for (int nf = 0; nf < 8; nf++) {
                uint32_t bf[2];
                bf[0] = Vs[(ks * 8 + tg) * VST + nf * 8 + gr];
                bf[1] = Vs[(ks * 8 + tg + 4) * VST + nf * 8 + gr];
                mma8(o[nf], a, bf);
            }
        }
        __syncwarp();   // P reads done before next iter overwrites
    }

    // ---- normalize + store [b, s, h*64 + d] ----
#pragma unroll
    for (int hf = 0; hf < 2; hf++) {
        const float inv = 1.0f / l_i[hf];
        const int srow = q0 + rb + gr + 8 * hf;
        const size_t ob = (size_t)(b * SEQL + srow) * 1024 + h * 64;
#pragma unroll
        for (int nf = 0; nf < 8; nf++) {
            const int col = nf * 8 + tg * 2;
            float2 v2 = make_float2(o[nf][2*hf] * inv, o[nf][2*hf+1] * inv);
            *(float2*)&out[ob + col] = v2;
        }
    }
}

// ---------------------------------------------------------------------------
extern "C" void kernel_launch(void* const* d_in, const int* in_sizes, int n_in,
                              void* d_out, int out_size)
{
    const float* x  = (const float*)d_in[0];
    const float* wq = (const float*)d_in[1];
    const float* wk = (const float*)d_in[2];
    const float* wv = (const float*)d_in[3];
    const float* wo = (const float*)d_in[4];
    const int*   tp = (const int*)d_in[5];
    float* out = (float*)d_out;

    float *q, *k, *v, *attn;
    cudaGetSymbolAddress((void**)&q, g_q);
    cudaGetSymbolAddress((void**)&k, g_k);
    cudaGetSymbolAddress((void**)&v, g_v);
    cudaGetSymbolAddress((void**)&attn, g_attn);

    // Qs(128*68) + Ks(64*68) + Vs(64*72) + Ps(8*16*68), u32 words
    const int flash_smem = (128*QKS + 64*QKS + 64*VST + 8*16*QKS) * (int)sizeof(uint32_t); // 105472
    cudaFuncSetAttribute(flash_mma, cudaFuncAttributeMaxDynamicSharedMemorySize,
                         flash_smem);

    dim3 pgrid(8, 32);   // N/128, M/128
    proj_mma<1><<<pgrid, 256>>>(x, wq, tp, q);
    proj_mma<1><<<pgrid, 256>>>(x, wk, tp, k);
    proj_mma<2><<<pgrid, 256>>>(x, wv, tp, v);
    flash_mma<<<dim3(16, 32), 256, flash_smem>>>(q, k, v, attn);
    proj_mma<0><<<pgrid, 256>>>(attn, wo, nullptr, out);
}

// round 8
// speedup vs baseline: 2.4406x; 1.0040x over previous
#include <cuda_runtime.h>
#include <math.h>
#include <stdint.h>

#define D_MODEL 1024
#define NHEADS  16
#define DKV     64
#define SEQL    2048
#define BATCH   2

// Scratch (allocation-free rule: __device__ globals)
__device__ float g_q[BATCH*NHEADS*SEQL*DKV];     // [b,h,s,d]  (tf32-rounded bits)
__device__ float g_k[BATCH*NHEADS*SEQL*DKV];
__device__ float g_v[BATCH*NHEADS*SEQL*DKV];
__device__ float g_attn[BATCH*SEQL*D_MODEL];     // [b,s,h*64+d]

// ---------------------------------------------------------------------------
// tf32 + cp.async helpers
// ---------------------------------------------------------------------------
__device__ __forceinline__ uint32_t f2tf(float f) {
    uint32_t r;
    asm("cvt.rna.tf32.f32 %0, %1;" : "=r"(r) : "f"(f));
    return r;
}

__device__ __forceinline__ void mma8(float* c, const uint32_t* a, const uint32_t* b) {
    asm volatile(
        "mma.sync.aligned.m16n8k8.row.col.f32.tf32.tf32.f32 "
        "{%0,%1,%2,%3}, {%4,%5,%6,%7}, {%8,%9}, {%0,%1,%2,%3};"
        : "+f"(c[0]), "+f"(c[1]), "+f"(c[2]), "+f"(c[3])
        : "r"(a[0]), "r"(a[1]), "r"(a[2]), "r"(a[3]), "r"(b[0]), "r"(b[1]));
}

__device__ __forceinline__ void cpa16(uint32_t dst, const void* src) {
    asm volatile("cp.async.ca.shared.global [%0], [%1], 16;" :: "r"(dst), "l"(src));
}
__device__ __forceinline__ void cpa_commit() {
    asm volatile("cp.async.commit_group;");
}
template<int N>
__device__ __forceinline__ void cpa_wait() {
    asm volatile("cp.async.wait_group %0;" :: "n"(N));
}

// ---------------------------------------------------------------------------
// Projection GEMM on tensor cores (tf32). Epilogue MODE 1/2 now stores
// tf32-ROUNDED floats (same values flash previously produced by rounding on
// load — numerically identical chain).
// ---------------------------------------------------------------------------
#define LDA 20

template<int MODE>
__global__ __launch_bounds__(256)
void proj_mma(const float* __restrict__ A, const float* __restrict__ W,
              const int* __restrict__ tpos, float* __restrict__ out)
{
    __shared__ uint32_t As[2][128 * LDA];
    __shared__ uint32_t Bs[2][128 * LDA];

    const int tid   = threadIdx.x;
    const int lane  = tid & 31;
    const int wid   = tid >> 5;
    const int warpM = wid >> 1;
    const int warpN = wid & 1;
    const int gr    = lane >> 2;
    const int tg    = lane & 3;
    const int m0    = blockIdx.y * 128;
    const int n0    = blockIdx.x * 128;

    const int lrow = tid >> 1;
    const int lc4  = (tid & 1) * 2;

    const float* aptr = A + (size_t)(m0 + lrow) * 1024 + lc4 * 4;
    const float* bptr = W + (size_t)(n0 + lrow) * 1024 + lc4 * 4;

    float c[2][8][4];
#pragma unroll
    for (int mt = 0; mt < 2; mt++)
#pragma unroll
        for (int nt = 0; nt < 8; nt++)
#pragma unroll
            for (int i = 0; i < 4; i++) c[mt][nt][i] = 0.0f;

    {
        float4 a0 = *(const float4*)(aptr);
        float4 a1 = *(const float4*)(aptr + 4);
        float4 b0 = *(const float4*)(bptr);
        float4 b1 = *(const float4*)(bptr + 4);
        uint32_t* as = &As[0][lrow * LDA + lc4 * 4];
        as[0] = f2tf(a0.x); as[1] = f2tf(a0.y); as[2] = f2tf(a0.z); as[3] = f2tf(a0.w);
        as[4] = f2tf(a1.x); as[5] = f2tf(a1.y); as[6] = f2tf(a1.z); as[7] = f2tf(a1.w);
        uint32_t* bs = &Bs[0][lrow * LDA + lc4 * 4];
        bs[0] = f2tf(b0.x); bs[1] = f2tf(b0.y); bs[2] = f2tf(b0.z); bs[3] = f2tf(b0.w);
        bs[4] = f2tf(b1.x); bs[5] = f2tf(b1.y); bs[6] = f2tf(b1.z); bs[7] = f2tf(b1.w);
    }
    __syncthreads();

    for (int kt = 0; kt < 64; kt++) {
        const int cur = kt & 1;

        float4 pa0, pa1, pb0, pb1;
        if (kt < 63) {
            const float* ap = aptr + (kt + 1) * 16;
            pa0 = *(const float4*)(ap);
            pa1 = *(const float4*)(ap + 4);
            const float* bp = bptr + (kt + 1) * 16;
            pb0 = *(const float4*)(bp);
            pb1 = *(const float4*)(bp + 4);
        }

        const uint32_t* as = As[cur];
        const uint32_t* bs = Bs[cur];
#pragma unroll
        for (int k8 = 0; k8 < 2; k8++) {
            const int kc = k8 * 8 + tg;
            uint32_t af[2][4];
#pragma unroll
            for (int mt = 0; mt < 2; mt++) {
                const int rb = warpM * 32 + mt * 16 + gr;
                af[mt][0] = as[rb * LDA + kc];
                af[mt][1] = as[(rb + 8) * LDA + kc];
                af[mt][2] = as[rb * LDA + kc + 4];
                af[mt][3] = as[(rb + 8) * LDA + kc + 4];
            }
            uint32_t bf[8][2];
#pragma unroll
            for (int nt = 0; nt < 8; nt++) {
                const int nb = warpN * 64 + nt * 8 + gr;
                bf[nt][0] = bs[nb * LDA + kc];
                bf[nt][1] = bs[nb * LDA + kc + 4];
            }
#pragma unroll
            for (int mt = 0; mt < 2; mt++)
#pragma unroll
                for (int nt = 0; nt < 8; nt++)
                    mma8(c[mt][nt], af[mt], bf[nt]);
        }

        if (kt < 63) {
            uint32_t* asd = &As[1 - cur][lrow * LDA + lc4 * 4];
            asd[0] = f2tf(pa0.x); asd[1] = f2tf(pa0.y); asd[2] = f2tf(pa0.z); asd[3] = f2tf(pa0.w);
            asd[4] = f2tf(pa1.x); asd[5] = f2tf(pa1.y); asd[6] = f2tf(pa1.z); asd[7] = f2tf(pa1.w);
            uint32_t* bsd = &Bs[1 - cur][lrow * LDA + lc4 * 4];
            bsd[0] = f2tf(pb0.x); bsd[1] = f2tf(pb0.y); bsd[2] = f2tf(pb0.z); bsd[3] = f2tf(pb0.w);
            bsd[4] = f2tf(pb1.x); bsd[5] = f2tf(pb1.y); bsd[6] = f2tf(pb1.z); bsd[7] = f2tf(pb1.w);
        }
        __syncthreads();
    }

#pragma unroll
    for (int mt = 0; mt < 2; mt++) {
        const int row0 = m0 + warpM * 32 + mt * 16 + gr;
#pragma unroll
        for (int half = 0; half < 2; half++) {
            const int row = row0 + half * 8;
            const int b = row >> 11;
            const int s = row & 2047;
            float p = 0.0f;
            if (MODE == 1) p = (float)tpos[s];
#pragma unroll
            for (int nt = 0; nt < 8; nt++) {
                float v0 = c[mt][nt][half * 2 + 0];
                float v1 = c[mt][nt][half * 2 + 1];
                const int col = n0 + warpN * 64 + nt * 8 + tg * 2;
                if (MODE == 0) {
                    out[(size_t)row * 1024 + col]     = v0;
                    out[(size_t)row * 1024 + col + 1] = v1;
                } else {
                    const int h  = col >> 6;
                    const int dd = col & 63;
                    if (MODE == 1) {
                        const int jj = dd >> 1;
                        float freq = 1.0f / powf(10000.0f, (float)(2 * jj) * (1.0f / 64.0f));
                        float sn, cs;
                        sincosf(p * freq, &sn, &cs);
                        float r0 = v0 * cs - v1 * sn;
                        float r1 = v1 * cs + v0 * sn;
                        v0 = r0; v1 = r1;
                    }
                    const int dst = ((b * NHEADS + h) * SEQL + s) * DKV + dd;
                    // store tf32-rounded bits (flash consumes raw)
                    out[dst]     = __uint_as_float(f2tf(v0));
                    out[dst + 1] = __uint_as_float(f2tf(v1));
                }
            }
        }
    }
}

// ---------------------------------------------------------------------------
// Flash attention v4: tf32 mma, 128-row Q tiles, 8 warps, cp.async
// double-buffered 32-row KV tiles (2-stage ring). Q/K/V arrive already
// tf32-rounded from the projection epilogues -> raw-bit copies.
// smem: Qs 128*68 | Kb 2*32*68 | Vb 2*32*72 | Ps 8*16*68  = 105472 B
// ---------------------------------------------------------------------------
#define QKS 68
#define VST 72
#define KBOFF (128 * QKS)
#define VBOFF (KBOFF + 2 * 32 * QKS)
#define PSOFF (VBOFF + 2 * 32 * VST)

__global__ __launch_bounds__(256)
void flash_mma(const float* __restrict__ Q, const float* __restrict__ K,
               const float* __restrict__ V, float* __restrict__ out)
{
    extern __shared__ uint32_t sm[];
    uint32_t* Qs = sm;
    uint32_t* Ps = sm + PSOFF;
    const uint32_t smem_u32 = (uint32_t)__cvta_generic_to_shared(sm);

    const int tid  = threadIdx.x;
    const int lane = tid & 31;
    const int wid  = tid >> 5;
    const int gr   = lane >> 2;    // 0..7
    const int tg   = lane & 3;     // 0..3
    const int qt   = 15 - blockIdx.x;        // heavy tiles first
    const int bh   = blockIdx.y;
    const int b    = bh >> 4;
    const int h    = bh & 15;
    const size_t base = (size_t)bh * SEQL * DKV;
    const int q0   = qt * 128;
    const int rb   = wid * 16;
    uint32_t* Pw   = Ps + wid * 16 * QKS;
    const int njt  = 4 * qt + 4;             // 32-row kv tiles

    // per-thread cp.async slots: i in {tid, tid+256} -> (row, col4)
    const int r0 = tid >> 4, c40 = (tid & 15) * 4;        // i = tid
    const int r1 = (tid + 256) >> 4, c41 = c40;           // i = tid+256

    // Load Q tile (raw bits, already tf32): 128 rows x 64 cols
    for (int i = tid; i < 2048; i += 256) {
        const int r = i >> 4, c4 = (i & 15) * 4;
        *(uint4*)&Qs[r * QKS + c4] =
            *(const uint4*)&Q[base + (size_t)(q0 + r) * 64 + c4];
    }

    // issue stage jt into buffer jt&1 (commit unconditionally)
    auto issue = [&](int jt) {
        if (jt < njt) {
            const int buf = jt & 1;
            const size_t krow = base + (size_t)(jt * 32) * 64;
            cpa16(smem_u32 + (KBOFF + buf * 32 * QKS + r0 * QKS + c40) * 4,
                  &K[krow + (size_t)r0 * 64 + c40]);
            cpa16(smem_u32 + (VBOFF + buf * 32 * VST + r0 * VST + c40) * 4,
                  &V[krow + (size_t)r0 * 64 + c40]);
            cpa16(smem_u32 + (KBOFF + buf * 32 * QKS + r1 * QKS + c41) * 4,
                  &K[krow + (size_t)r1 * 64 + c41]);
            cpa16(smem_u32 + (VBOFF + buf * 32 * VST + r1 * VST + c41) * 4,
                  &V[krow + (size_t)r1 * 64 + c41]);
        }
        cpa_commit();
    };

    issue(0);
    issue(1);

    float o[8][4];
#pragma unroll
    for (int nf = 0; nf < 8; nf++)
#pragma unroll
        for (int i = 0; i < 4; i++) o[nf][i] = 0.0f;
    float m_i[2] = {-1e30f, -1e30f};
    float l_i[2] = {0.0f, 0.0f};

    for (int jt = 0; jt < njt; jt++) {
        const int buf = jt & 1;
        const uint32_t* Kb = sm + KBOFF + buf * 32 * QKS;
        const uint32_t* Vb = sm + VBOFF + buf * 32 * VST;

        cpa_wait<1>();        // stage jt landed
        __syncthreads();      // visible to all; Q store (iter0) also covered

        // ---- S = Q K^T : warp rows [rb,rb+16) x 32 kv cols ----
        float s[4][4];
#pragma unroll
        for (int nf = 0; nf < 4; nf++)
#pragma unroll
            for (int i = 0; i < 4; i++) s[nf][i] = 0.0f;

#pragma unroll
        for (int ks = 0; ks < 8; ks++) {
            const int kc = ks * 8 + tg;
            uint32_t a[4];
            a[0] = Qs[(rb + gr) * QKS + kc];
            a[1] = Qs[(rb + gr + 8) * QKS + kc];
            a[2] = Qs[(rb + gr) * QKS + kc + 4];
            a[3] = Qs[(rb + gr + 8) * QKS + kc + 4];
#pragma unroll
            for (int nf = 0; nf < 4; nf++) {
                uint32_t bf[2];
                bf[0] = Kb[(nf * 8 + gr) * QKS + kc];
                bf[1] = Kb[(nf * 8 + gr) * QKS + kc + 4];
                mma8(s[nf], a, bf);
            }
        }

        // ---- scale + causal mask (tiles overlapping the diagonal) ----
        const float scale = 0.125f;
        if (jt >= 4 * qt) {
#pragma unroll
            for (int nf = 0; nf < 4; nf++) {
                const int colg = jt * 32 + nf * 8 + tg * 2;
#pragma unroll
                for (int hf = 0; hf < 2; hf++) {
                    const int rowg = q0 + rb + gr + 8 * hf;
                    s[nf][2*hf]   = (colg     > rowg) ? -1e30f : s[nf][2*hf]   * scale;
                    s[nf][2*hf+1] = (colg + 1 > rowg) ? -1e30f : s[nf][2*hf+1] * scale;
                }
            }
        } else {
#pragma unroll
            for (int nf = 0; nf < 4; nf++)
#pragma unroll
                for (int i = 0; i < 4; i++) s[nf][i] *= scale;
        }

        // ---- online softmax ----
        float p[4][4];
#pragma unroll
        for (int hf = 0; hf < 2; hf++) {
            float mx = -1e30f;
#pragma unroll
            for (int nf = 0; nf < 4; nf++)
                mx = fmaxf(mx, fmaxf(s[nf][2*hf], s[nf][2*hf+1]));
            mx = fmaxf(mx, __shfl_xor_sync(0xffffffffu, mx, 1));
            mx = fmaxf(mx, __shfl_xor_sync(0xffffffffu, mx, 2));
            const float mn = fmaxf(m_i[hf], mx);
            const float alpha = __expf(m_i[hf] - mn);
            m_i[hf] = mn;
            float rs = 0.0f;
#pragma unroll
            for (int nf = 0; nf < 4; nf++) {
                float p0 = __expf(s[nf][2*hf]   - mn);
                float p1 = __expf(s[nf][2*hf+1] - mn);
                p[nf][2*hf] = p0; p[nf][2*hf+1] = p1;
                rs += p0 + p1;
            }
            rs += __shfl_xor_sync(0xffffffffu, rs, 1);
            rs += __shfl_xor_sync(0xffffffffu, rs, 2);
            l_i[hf] = l_i[hf] * alpha + rs;
#pragma unroll
            for (int nf = 0; nf < 8; nf++) {
                o[nf][2*hf]   *= alpha;
                o[nf][2*hf+1] *= alpha;
            }
        }

        // ---- stage P (16x32) in warp-private smem ----
#pragma unroll
        for (int nf = 0; nf < 4; nf++) {
            const int col = nf * 8 + tg * 2;
            Pw[gr * QKS + col]           = f2tf(p[nf][0]);
            Pw[gr * QKS + col + 1]       = f2tf(p[nf][1]);
            Pw[(gr + 8) * QKS + col]     = f2tf(p[nf][2]);
            Pw[(gr + 8) * QKS + col + 1] = f2tf(p[nf][3]);
        }
        __syncwarp();

        // ---- O += P V  (P 16x32, V 32x64) ----
#pragma unroll
        for (int ks = 0; ks < 4; ks++) {
            const int kc = ks * 8 + tg;
            uint32_t a[4];
            a[0] = Pw[gr * QKS + kc];
            a[1] = Pw[(gr + 8) * QKS + kc];
            a[2] = Pw[gr * QKS + kc + 4];
            a[3] = Pw[(gr + 8) * QKS + kc + 4];
#pragma unroll
            for (int nf = 0; nf < 8; nf++) {
                uint32_t bf[2];
                bf[0] = Vb[(ks * 8 + tg) * VST + nf * 8 + gr];
                bf[1] = Vb[(ks * 8 + tg + 4) * VST + nf * 8 + gr];
                mma8(o[nf], a, bf);
            }
        }

        __syncthreads();      // all warps done with buffer `buf`
        issue(jt + 2);        // refill it
    }

    // ---- normalize + store [b, s, h*64 + d] ----
#pragma unroll
    for (int hf = 0; hf < 2; hf++) {
        const float inv = 1.0f / l_i[hf];
        const int srow = q0 + rb + gr + 8 * hf;
        const size_t ob = (size_t)(b * SEQL + srow) * 1024 + h * 64;
#pragma unroll
        for (int nf = 0; nf < 8; nf++) {
            const int col = nf * 8 + tg * 2;
            float2 v2 = make_float2(o[nf][2*hf] * inv, o[nf][2*hf+1] * inv);
            *(float2*)&out[ob + col] = v2;
        }
    }
}

// ---------------------------------------------------------------------------
extern "C" void kernel_launch(void* const* d_in, const int* in_sizes, int n_in,
                              void* d_out, int out_size)
{
    const float* x  = (const float*)d_in[0];
    const float* wq = (const float*)d_in[1];
    const float* wk = (const float*)d_in[2];
    const float* wv = (const float*)d_in[3];
    const float* wo = (const float*)d_in[4];
    const int*   tp = (const int*)d_in[5];
    float* out = (float*)d_out;

    float *q, *k, *v, *attn;
    cudaGetSymbolAddress((void**)&q, g_q);
    cudaGetSymbolAddress((void**)&k, g_k);
    cudaGetSymbolAddress((void**)&v, g_v);
    cudaGetSymbolAddress((void**)&attn, g_attn);

    const int flash_smem = (PSOFF + 8 * 16 * QKS) * (int)sizeof(uint32_t); // 105472
    cudaFuncSetAttribute(flash_mma, cudaFuncAttributeMaxDynamicSharedMemorySize,
                         flash_smem);

    dim3 pgrid(8, 32);   // N/128, M/128
    proj_mma<1><<<pgrid, 256>>>(x, wq, tp, q);
    proj_mma<1><<<pgrid, 256>>>(x, wk, tp, k);
    proj_mma<2><<<pgrid, 256>>>(x, wv, tp, v);
    flash_mma<<<dim3(16, 32), 256, flash_smem>>>(q, k, v, attn);
    proj_mma<0><<<pgrid, 256>>>(attn, wo, nullptr, out);
}

// round 9
// speedup vs baseline: 2.6306x; 1.0779x over previous
#include <cuda_runtime.h>
#include <math.h>
#include <stdint.h>

#define D_MODEL 1024
#define NHEADS  16
#define DKV     64
#define SEQL    2048
#define BATCH   2

// Scratch (allocation-free rule: __device__ globals)
__device__ float g_q[BATCH*NHEADS*SEQL*DKV];     // [b,h,s,d]  (tf32-rounded bits)
__device__ float g_k[BATCH*NHEADS*SEQL*DKV];
__device__ float g_v[BATCH*NHEADS*SEQL*DKV];
__device__ float g_attn[BATCH*SEQL*D_MODEL];     // [b,s,h*64+d]

// ---------------------------------------------------------------------------
// tf32 / mma / ldmatrix / cp.async helpers
// ---------------------------------------------------------------------------
__device__ __forceinline__ uint32_t f2tf(float f) {
    uint32_t r;
    asm("cvt.rna.tf32.f32 %0, %1;" : "=r"(r) : "f"(f));
    return r;
}

__device__ __forceinline__ void mma8(float* c, const uint32_t* a, const uint32_t* b) {
    asm volatile(
        "mma.sync.aligned.m16n8k8.row.col.f32.tf32.tf32.f32 "
        "{%0,%1,%2,%3}, {%4,%5,%6,%7}, {%8,%9}, {%0,%1,%2,%3};"
        : "+f"(c[0]), "+f"(c[1]), "+f"(c[2]), "+f"(c[3])
        : "r"(a[0]), "r"(a[1]), "r"(a[2]), "r"(a[3]), "r"(b[0]), "r"(b[1]));
}

// warp-collective: 4x (8 rows x 16B) tiles; lane L gets word (L&3) of row (L>>2)
__device__ __forceinline__ void ldsm4(uint32_t* r, uint32_t addr) {
    asm volatile("ldmatrix.sync.aligned.m8n8.x4.shared.b16 {%0,%1,%2,%3}, [%4];"
        : "=r"(r[0]), "=r"(r[1]), "=r"(r[2]), "=r"(r[3]) : "r"(addr));
}

__device__ __forceinline__ void cpa16(uint32_t dst, const void* src) {
    asm volatile("cp.async.ca.shared.global [%0], [%1], 16;" :: "r"(dst), "l"(src));
}
__device__ __forceinline__ void cpa_commit() {
    asm volatile("cp.async.commit_group;");
}
template<int N>
__device__ __forceinline__ void cpa_wait() {
    asm volatile("cp.async.wait_group %0;" :: "n"(N));
}

// ---------------------------------------------------------------------------
// Projection GEMM on tensor cores (tf32), ldmatrix fragment loads.
//   C[m,n] = sum_k A[m,k] * W[n,k]; M=4096, N=1024, K=1024.
//   Block 128x128, BK=16, 256 thr (8 warps), warp tile 32x64.
// MODE 0: plain store; MODE 1: head layout + RoPE (tf32-rounded store);
// MODE 2: head layout (tf32-rounded store).
// ---------------------------------------------------------------------------
#define LDA 20
#define ABUFB (128 * LDA * 4)   // bytes per A/B buffer

template<int MODE>
__global__ __launch_bounds__(256)
void proj_mma(const float* __restrict__ A, const float* __restrict__ W,
              const int* __restrict__ tpos, float* __restrict__ out)
{
    __shared__ uint32_t As[2][128 * LDA];
    __shared__ uint32_t Bs[2][128 * LDA];

    const int tid   = threadIdx.x;
    const int lane  = tid & 31;
    const int wid   = tid >> 5;
    const int warpM = wid >> 1;
    const int warpN = wid & 1;
    const int gr    = lane >> 2;
    const int tg    = lane & 3;
    const int m0    = blockIdx.y * 128;
    const int n0    = blockIdx.x * 128;

    const int lrow = tid >> 1;
    const int lc4  = (tid & 1) * 2;

    const float* aptr = A + (size_t)(m0 + lrow) * 1024 + lc4 * 4;
    const float* bptr = W + (size_t)(n0 + lrow) * 1024 + lc4 * 4;

    // ldmatrix per-lane offsets (bytes within one buffer)
    const int s8 = lane >> 3, j8 = lane & 7;
    uint32_t aOff[2], bOff[4];
#pragma unroll
    for (int mt = 0; mt < 2; mt++)
        aOff[mt] = ((warpM * 32 + mt * 16 + (s8 & 1) * 8 + j8) * LDA + (s8 >> 1) * 4) * 4;
#pragma unroll
    for (int ntp = 0; ntp < 4; ntp++)
        bOff[ntp] = ((warpN * 64 + ntp * 16 + (s8 >> 1) * 8 + j8) * LDA + (s8 & 1) * 4) * 4;

    const uint32_t asBase = (uint32_t)__cvta_generic_to_shared(&As[0][0]);
    const uint32_t bsBase = (uint32_t)__cvta_generic_to_shared(&Bs[0][0]);

    float c[2][8][4];
#pragma unroll
    for (int mt = 0; mt < 2; mt++)
#pragma unroll
        for (int nt = 0; nt < 8; nt++)
#pragma unroll
            for (int i = 0; i < 4; i++) c[mt][nt][i] = 0.0f;

    {
        float4 a0 = *(const float4*)(aptr);
        float4 a1 = *(const float4*)(aptr + 4);
        float4 b0 = *(const float4*)(bptr);
        float4 b1 = *(const float4*)(bptr + 4);
        uint32_t* as = &As[0][lrow * LDA + lc4 * 4];
        as[0] = f2tf(a0.x); as[1] = f2tf(a0.y); as[2] = f2tf(a0.z); as[3] = f2tf(a0.w);
        as[4] = f2tf(a1.x); as[5] = f2tf(a1.y); as[6] = f2tf(a1.z); as[7] = f2tf(a1.w);
        uint32_t* bs = &Bs[0][lrow * LDA + lc4 * 4];
        bs[0] = f2tf(b0.x); bs[1] = f2tf(b0.y); bs[2] = f2tf(b0.z); bs[3] = f2tf(b0.w);
        bs[4] = f2tf(b1.x); bs[5] = f2tf(b1.y); bs[6] = f2tf(b1.z); bs[7] = f2tf(b1.w);
    }
    __syncthreads();

    for (int kt = 0; kt < 64; kt++) {
        const int cur = kt & 1;

        float4 pa0, pa1, pb0, pb1;
        if (kt < 63) {
            const float* ap = aptr + (kt + 1) * 16;
            pa0 = *(const float4*)(ap);
            pa1 = *(const float4*)(ap + 4);
            const float* bp = bptr + (kt + 1) * 16;
            pb0 = *(const float4*)(bp);
            pb1 = *(const float4*)(bp + 4);
        }

        const uint32_t aB = asBase + cur * ABUFB;
        const uint32_t bB = bsBase + cur * ABUFB;
#pragma unroll
        for (int k8 = 0; k8 < 2; k8++) {
            uint32_t af[2][4];
            ldsm4(af[0], aB + aOff[0] + k8 * 32);
            ldsm4(af[1], aB + aOff[1] + k8 * 32);
            uint32_t bq[4][4];
#pragma unroll
            for (int ntp = 0; ntp < 4; ntp++)
                ldsm4(bq[ntp], bB + bOff[ntp] + k8 * 32);
#pragma unroll
            for (int mt = 0; mt < 2; mt++)
#pragma unroll
                for (int nt = 0; nt < 8; nt++)
                    mma8(c[mt][nt], af[mt], &bq[nt >> 1][(nt & 1) * 2]);
        }

        if (kt < 63) {
            uint32_t* asd = &As[1 - cur][lrow * LDA + lc4 * 4];
            asd[0] = f2tf(pa0.x); asd[1] = f2tf(pa0.y); asd[2] = f2tf(pa0.z); asd[3] = f2tf(pa0.w);
            asd[4] = f2tf(pa1.x); asd[5] = f2tf(pa1.y); asd[6] = f2tf(pa1.z); asd[7] = f2tf(pa1.w);
            uint32_t* bsd = &Bs[1 - cur][lrow * LDA + lc4 * 4];
            bsd[0] = f2tf(pb0.x); bsd[1] = f2tf(pb0.y); bsd[2] = f2tf(pb0.z); bsd[3] = f2tf(pb0.w);
            bsd[4] = f2tf(pb1.x); bsd[5] = f2tf(pb1.y); bsd[6] = f2tf(pb1.z); bsd[7] = f2tf(pb1.w);
        }
        __syncthreads();
    }

#pragma unroll
    for (int mt = 0; mt < 2; mt++) {
        const int row0 = m0 + warpM * 32 + mt * 16 + gr;
#pragma unroll
        for (int half = 0; half < 2; half++) {
            const int row = row0 + half * 8;
            const int b = row >> 11;
            const int s = row & 2047;
            float p = 0.0f;
            if (MODE == 1) p = (float)tpos[s];
#pragma unroll
            for (int nt = 0; nt < 8; nt++) {
                float v0 = c[mt][nt][half * 2 + 0];
                float v1 = c[mt][nt][half * 2 + 1];
                const int col = n0 + warpN * 64 + nt * 8 + tg * 2;
                if (MODE == 0) {
                    out[(size_t)row * 1024 + col]     = v0;
                    out[(size_t)row * 1024 + col + 1] = v1;
                } else {
                    const int h  = col >> 6;
                    const int dd = col & 63;
                    if (MODE == 1) {
                        const int jj = dd >> 1;
                        float freq = 1.0f / powf(10000.0f, (float)(2 * jj) * (1.0f / 64.0f));
                        float sn, cs;
                        sincosf(p * freq, &sn, &cs);
                        float r0 = v0 * cs - v1 * sn;
                        float r1 = v1 * cs + v0 * sn;
                        v0 = r0; v1 = r1;
                    }
                    const int dst = ((b * NHEADS + h) * SEQL + s) * DKV + dd;
                    out[dst]     = __uint_as_float(f2tf(v0));
                    out[dst + 1] = __uint_as_float(f2tf(v1));
                }
            }
        }
    }
}

// ---------------------------------------------------------------------------
// Flash attention v5: tf32 mma + ldmatrix fragments, 128-row Q tiles, 8 warps,
// cp.async double-buffered 32-row KV tiles. Q/K/V arrive tf32-rounded.
// smem: Qs 128*68 | Kb 2*32*68 | Vb 2*32*72 | Ps 8*16*68  = 105472 B
// ---------------------------------------------------------------------------
#define QKS 68
#define VST 72
#define KBOFF (128 * QKS)
#define VBOFF (KBOFF + 2 * 32 * QKS)
#define PSOFF (VBOFF + 2 * 32 * VST)

__global__ __launch_bounds__(256)
void flash_mma(const float* __restrict__ Q, const float* __restrict__ K,
               const float* __restrict__ V, float* __restrict__ out)
{
    extern __shared__ uint32_t sm[];
    uint32_t* Qs = sm;
    uint32_t* Ps = sm + PSOFF;
    const uint32_t smem_u32 = (uint32_t)__cvta_generic_to_shared(sm);

    const int tid  = threadIdx.x;
    const int lane = tid & 31;
    const int wid  = tid >> 5;
    const int gr   = lane >> 2;    // 0..7
    const int tg   = lane & 3;     // 0..3
    const int qt   = 15 - blockIdx.x;        // heavy tiles first
    const int bh   = blockIdx.y;
    const int b    = bh >> 4;
    const int h    = bh & 15;
    const size_t base = (size_t)bh * SEQL * DKV;
    const int q0   = qt * 128;
    const int rb   = wid * 16;
    uint32_t* Pw   = Ps + wid * 16 * QKS;
    const int njt  = 4 * qt + 4;             // 32-row kv tiles

    // ldmatrix lane offsets (bytes)
    const int s8 = lane >> 3, j8 = lane & 7;
    const uint32_t qOff = smem_u32 +
        ((rb + (s8 & 1) * 8 + j8) * QKS + (s8 >> 1) * 4) * 4;
    uint32_t kOff[2];
#pragma unroll
    for (int nfp = 0; nfp < 2; nfp++)
        kOff[nfp] = ((nfp * 16 + (s8 >> 1) * 8 + j8) * QKS + (s8 & 1) * 4) * 4;
    const uint32_t pOff = smem_u32 + (PSOFF + wid * 16 * QKS) * 4 +
        (((s8 & 1) * 8 + j8) * QKS + (s8 >> 1) * 4) * 4;

    // per-thread cp.async slots
    const int r0 = tid >> 4, c40 = (tid & 15) * 4;
    const int r1 = (tid + 256) >> 4, c41 = c40;

    // Load Q tile (raw bits, already tf32): 128 x 64
    for (int i = tid; i < 2048; i += 256) {
        const int r = i >> 4, c4 = (i & 15) * 4;
        *(uint4*)&Qs[r * QKS + c4] =
            *(const uint4*)&Q[base + (size_t)(q0 + r) * 64 + c4];
    }

    auto issue = [&](int jt) {
        if (jt < njt) {
            const int buf = jt & 1;
            const size_t krow = base + (size_t)(jt * 32) * 64;
            cpa16(smem_u32 + (KBOFF + buf * 32 * QKS + r0 * QKS + c40) * 4,
                  &K[krow + (size_t)r0 * 64 + c40]);
            cpa16(smem_u32 + (VBOFF + buf * 32 * VST + r0 * VST + c40) * 4,
                  &V[krow + (size_t)r0 * 64 + c40]);
            cpa16(smem_u32 + (KBOFF + buf * 32 * QKS + r1 * QKS + c41) * 4,
                  &K[krow + (size_t)r1 * 64 + c41]);
            cpa16(smem_u32 + (VBOFF + buf * 32 * VST + r1 * VST + c41) * 4,
                  &V[krow + (size_t)r1 * 64 + c41]);
        }
        cpa_commit();
    };

    issue(0);
    issue(1);

    float o[8][4];
#pragma unroll
    for (int nf = 0; nf < 8; nf++)
#pragma unroll
        for (int i = 0; i < 4; i++) o[nf][i] = 0.0f;
    float m_i[2] = {-1e30f, -1e30f};
    float l_i[2] = {0.0f, 0.0f};

    for (int jt = 0; jt < njt; jt++) {
        const int buf = jt & 1;
        const uint32_t* Vb = sm + VBOFF + buf * 32 * VST;
        const uint32_t kbA = smem_u32 + (KBOFF + buf * 32 * QKS) * 4;

        cpa_wait<1>();
        __syncthreads();

        // ---- S = Q K^T : warp rows [rb,rb+16) x 32 kv cols ----
        float s[4][4];
#pragma unroll
        for (int nf = 0; nf < 4; nf++)
#pragma unroll
            for (int i = 0; i < 4; i++) s[nf][i] = 0.0f;

#pragma unroll
        for (int ks = 0; ks < 8; ks++) {
            uint32_t a[4];
            ldsm4(a, qOff + ks * 32);
            uint32_t kq[2][4];
            ldsm4(kq[0], kbA + kOff[0] + ks * 32);
            ldsm4(kq[1], kbA + kOff[1] + ks * 32);
            mma8(s[0], a, &kq[0][0]);
            mma8(s[1], a, &kq[0][2]);
            mma8(s[2], a, &kq[1][0]);
            mma8(s[3], a, &kq[1][2]);
        }

        // ---- scale + causal mask ----
        const float scale = 0.125f;
        if (jt >= 4 * qt) {
#pragma unroll
            for (int nf = 0; nf < 4; nf++) {
                const int colg = jt * 32 + nf * 8 + tg * 2;
#pragma unroll
                for (int hf = 0; hf < 2; hf++) {
                    const int rowg = q0 + rb + gr + 8 * hf;
                    s[nf][2*hf]   = (colg     > rowg) ? -1e30f : s[nf][2*hf]   * scale;
                    s[nf][2*hf+1] = (colg + 1 > rowg) ? -1e30f : s[nf][2*hf+1] * scale;
                }
            }
        } else {
#pragma unroll
            for (int nf = 0; nf < 4; nf++)
#pragma unroll
                for (int i = 0; i < 4; i++) s[nf][i] *= scale;
        }

        // ---- online softmax ----
        float p[4][4];
#pragma unroll
        for (int hf = 0; hf < 2; hf++) {
            float mx = -1e30f;
#pragma unroll
            for (int nf = 0; nf < 4; nf++)
                mx = fmaxf(mx, fmaxf(s[nf][2*hf], s[nf][2*hf+1]));
            mx = fmaxf(mx, __shfl_xor_sync(0xffffffffu, mx, 1));
            mx = fmaxf(mx, __shfl_xor_sync(0xffffffffu, mx, 2));
            const float mn = fmaxf(m_i[hf], mx);
            const float alpha = __expf(m_i[hf] - mn);
            m_i[hf] = mn;
            float rs = 0.0f;
#pragma unroll
            for (int nf = 0; nf < 4; nf++) {
                float p0 = __expf(s[nf][2*hf]   - mn);
                float p1 = __expf(s[nf][2*hf+1] - mn);
                p[nf][2*hf] = p0; p[nf][2*hf+1] = p1;
                rs += p0 + p1;
            }
            rs += __shfl_xor_sync(0xffffffffu, rs, 1);
            rs += __shfl_xor_sync(0xffffffffu, rs, 2);
            l_i[hf] = l_i[hf] * alpha + rs;
#pragma unroll
            for (int nf = 0; nf < 8; nf++) {
                o[nf][2*hf]   *= alpha;
                o[nf][2*hf+1] *= alpha;
            }
        }

        // ---- stage P (16x32) in warp-private smem (STS.64) ----
#pragma unroll
        for (int nf = 0; nf < 4; nf++) {
            const int col = nf * 8 + tg * 2;
            *(uint2*)&Pw[gr * QKS + col]       = make_uint2(f2tf(p[nf][0]), f2tf(p[nf][1]));
            *(uint2*)&Pw[(gr + 8) * QKS + col] = make_uint2(f2tf(p[nf][2]), f2tf(p[nf][3]));
        }
        __syncwarp();

        // ---- O += P V  (P 16x32 via ldmatrix, V 32x64 scalar) ----
#pragma unroll
        for (int ks = 0; ks < 4; ks++) {
            uint32_t a[4];
            ldsm4(a, pOff + ks * 32);
#pragma unroll
            for (int nf = 0; nf < 8; nf++) {
                uint32_t bf[2];
                bf[0] = Vb[(ks * 8 + tg) * VST + nf * 8 + gr];
                bf[1] = Vb[(ks * 8 + tg + 4) * VST + nf * 8 + gr];
                mma8(o[nf], a, bf);
            }
        }

        __syncthreads();
        issue(jt + 2);
    }

    // ---- normalize + store [b, s, h*64 + d] ----
#pragma unroll
    for (int hf = 0; hf < 2; hf++) {
        const float inv = 1.0f / l_i[hf];
        const int srow = q0 + rb + gr + 8 * hf;
        const size_t ob = (size_t)(b * SEQL + srow) * 1024 + h * 64;
#pragma unroll
        for (int nf = 0; nf < 8; nf++) {
            const int col = nf * 8 + tg * 2;
            float2 v2 = make_float2(o[nf][2*hf] * inv, o[nf][2*hf+1] * inv);
            *(float2*)&out[ob + col] = v2;
        }
    }
}

// ---------------------------------------------------------------------------
extern "C" void kernel_launch(void* const* d_in, const int* in_sizes, int n_in,
                              void* d_out, int out_size)
{
    const float* x  = (const float*)d_in[0];
    const float* wq = (const float*)d_in[1];
    const float* wk = (const float*)d_in[2];
    const float* wv = (const float*)d_in[3];
    const float* wo = (const float*)d_in[4];
    const int*   tp = (const int*)d_in[5];
    float* out = (float*)d_out;

    float *q, *k, *v, *attn;
    cudaGetSymbolAddress((void**)&q, g_q);
    cudaGetSymbolAddress((void**)&k, g_k);
    cudaGetSymbolAddress((void**)&v, g_v);
    cudaGetSymbolAddress((void**)&attn, g_attn);

    const int flash_smem = (PSOFF + 8 * 16 * QKS) * (int)sizeof(uint32_t); // 105472
    cudaFuncSetAttribute(flash_mma, cudaFuncAttributeMaxDynamicSharedMemorySize,
                         flash_smem);

    dim3 pgrid(8, 32);   // N/128, M/128
    proj_mma<1><<<pgrid, 256>>>(x, wq, tp, q);
    proj_mma<1><<<pgrid, 256>>>(x, wk, tp, k);
    proj_mma<2><<<pgrid, 256>>>(x, wv, tp, v);
    flash_mma<<<dim3(16, 32), 256, flash_smem>>>(q, k, v, attn);
    proj_mma<0><<<pgrid, 256>>>(attn, wo, nullptr, out);
}

// round 10
// speedup vs baseline: 3.4112x; 1.2967x over previous
#include <cuda_runtime.h>
#include <math.h>
#include <stdint.h>

#define D_MODEL 1024
#define NHEADS  16
#define DKV     64
#define SEQL    2048
#define BATCH   2

// Scratch (allocation-free rule: __device__ globals)
__device__ float g_xr[4096*1024];                // x, tf32-rounded bits
__device__ float g_w[3*1024*1024];               // wq|wk|wv rounded
__device__ float g_wor[1024*1024];               // wo rounded
__device__ float g_q[BATCH*NHEADS*SEQL*DKV];     // [b,h,s,d]  tf32 bits
__device__ float g_k[BATCH*NHEADS*SEQL*DKV];     // [b,h,s,d]  tf32 bits
__device__ float g_v[BATCH*NHEADS*SEQL*DKV];     // [b,h,d,s]  tf32 bits (TRANSPOSED)
__device__ float g_attn[BATCH*SEQL*D_MODEL];     // [b,s,h*64+d] tf32 bits

// ---------------------------------------------------------------------------
// tf32 / mma / ldmatrix / cp.async helpers
// ---------------------------------------------------------------------------
__device__ __forceinline__ uint32_t f2tf(float f) {
    uint32_t r;
    asm("cvt.rna.tf32.f32 %0, %1;" : "=r"(r) : "f"(f));
    return r;
}

__device__ __forceinline__ void mma8(float* c, const uint32_t* a, const uint32_t* b) {
    asm volatile(
        "mma.sync.aligned.m16n8k8.row.col.f32.tf32.tf32.f32 "
        "{%0,%1,%2,%3}, {%4,%5,%6,%7}, {%8,%9}, {%0,%1,%2,%3};"
        : "+f"(c[0]), "+f"(c[1]), "+f"(c[2]), "+f"(c[3])
        : "r"(a[0]), "r"(a[1]), "r"(a[2]), "r"(a[3]), "r"(b[0]), "r"(b[1]));
}

__device__ __forceinline__ void ldsm4(uint32_t* r, uint32_t addr) {
    asm volatile("ldmatrix.sync.aligned.m8n8.x4.shared.b16 {%0,%1,%2,%3}, [%4];"
        : "=r"(r[0]), "=r"(r[1]), "=r"(r[2]), "=r"(r[3]) : "r"(addr));
}

__device__ __forceinline__ void cpa16(uint32_t dst, const void* src) {
    asm volatile("cp.async.ca.shared.global [%0], [%1], 16;" :: "r"(dst), "l"(src));
}
__device__ __forceinline__ void cpa_commit() {
    asm volatile("cp.async.commit_group;");
}
template<int N>
__device__ __forceinline__ void cpa_wait() {
    asm volatile("cp.async.wait_group %0;" :: "n"(N));
}

// ---------------------------------------------------------------------------
// Pre-round: x, wq|wk|wv, wo -> tf32 bits in scratch (grid-stride, float4)
// ---------------------------------------------------------------------------
__device__ __forceinline__ void round4(float* dst, const float* src, int i) {
    float4 a = ((const float4*)src)[i];
    uint4 r = make_uint4(f2tf(a.x), f2tf(a.y), f2tf(a.z), f2tf(a.w));
    ((uint4*)dst)[i] = r;
}

__global__ __launch_bounds__(256)
void preround(const float* __restrict__ x,  const float* __restrict__ wq,
              const float* __restrict__ wk, const float* __restrict__ wv,
              const float* __restrict__ wo)
{
    const int t = blockIdx.x * 256 + threadIdx.x;
    const int stride = gridDim.x * 256;
    for (int i = t; i < 1048576; i += stride) round4(g_xr, x, i);        // 4096x1024
    for (int i = t; i < 262144;  i += stride) round4(g_w,            wq, i);
    for (int i = t; i < 262144;  i += stride) round4(g_w + 1048576,  wk, i);
    for (int i = t; i < 262144;  i += stride) round4(g_w + 2097152,  wv, i);
    for (int i = t; i < 262144;  i += stride) round4(g_wor,          wo, i);
}

// ---------------------------------------------------------------------------
// Projection GEMM: cp.async staged raw tf32 bits + ldmatrix + mma.
//   C[m,n] = sum_k A[m,k]*W[n,k]; block 128x128, BK=16, 8 warps.
// FUSED=1: QKV fused (blockIdx.x: which=x>>3, n0=(x&7)*128); epilogues:
//   which 0/1 -> RoPE + [b,h,s,d] tf32 store; which 2 -> [b,h,d,s] tf32 store.
// FUSED=0: out-projection, plain fp32 store to outp.
// ---------------------------------------------------------------------------
#define LDA 20
#define ABUFB (128 * LDA * 4)   // bytes per stage buffer

template<int FUSED>
__global__ __launch_bounds__(256)
void proj_cp(const int* __restrict__ tpos, float* __restrict__ outp)
{
    __shared__ uint32_t As[2][128 * LDA];
    __shared__ uint32_t Bs[2][128 * LDA];

    const int tid   = threadIdx.x;
    const int lane  = tid & 31;
    const int wid   = tid >> 5;
    const int warpM = wid >> 1;
    const int warpN = wid & 1;
    const int gr    = lane >> 2;
    const int tg    = lane & 3;
    const int m0    = blockIdx.y * 128;

    int which, n0;
    const float *A, *W;
    if (FUSED) {
        which = blockIdx.x >> 3;
        n0 = (blockIdx.x & 7) * 128;
        A = g_xr;
        W = g_w + (size_t)which * 1048576;
    } else {
        which = -1;
        n0 = blockIdx.x * 128;
        A = g_attn;
        W = g_wor;
    }

    // cp.async mapping: 512 chunks per matrix per stage; thread owns tid, tid+256
    const int rA0 = tid >> 2, wA0 = (tid & 3) * 4;   // row 0..63
    const int rA1 = rA0 + 64;

    const uint32_t asB = (uint32_t)__cvta_generic_to_shared(&As[0][0]);
    const uint32_t bsB = (uint32_t)__cvta_generic_to_shared(&Bs[0][0]);

    // ldmatrix per-lane offsets (bytes within one buffer)
    const int s8 = lane >> 3, j8 = lane & 7;
    uint32_t aOff[2], bOff[4];
#pragma unroll
    for (int mt = 0; mt < 2; mt++)
        aOff[mt] = ((warpM * 32 + mt * 16 + (s8 & 1) * 8 + j8) * LDA + (s8 >> 1) * 4) * 4;
#pragma unroll
    for (int ntp = 0; ntp < 4; ntp++)
        bOff[ntp] = ((warpN * 64 + ntp * 16 + (s8 >> 1) * 8 + j8) * LDA + (s8 & 1) * 4) * 4;

    auto issue = [&](int kt) {
        if (kt < 64) {
            const int buf = kt & 1;
            const float* a = A + (size_t)(m0 + rA0) * 1024 + kt * 16 + wA0;
            cpa16(asB + (buf * 128 * LDA + rA0 * LDA + wA0) * 4, a);
            cpa16(asB + (buf * 128 * LDA + rA1 * LDA + wA0) * 4, a + 64 * 1024);
            const float* w = W + (size_t)(n0 + rA0) * 1024 + kt * 16 + wA0;
            cpa16(bsB + (buf * 128 * LDA + rA0 * LDA + wA0) * 4, w);
            cpa16(bsB + (buf * 128 * LDA + rA1 * LDA + wA0) * 4, w + 64 * 1024);
        }
        cpa_commit();
    };

    float c[2][8][4];
#pragma unroll
    for (int mt = 0; mt < 2; mt++)
#pragma unroll
        for (int nt = 0; nt < 8; nt++)
#pragma unroll
            for (int i = 0; i < 4; i++) c[mt][nt][i] = 0.0f;

    issue(0);
    issue(1);

    for (int kt = 0; kt < 64; kt++) {
        cpa_wait<1>();
        __syncthreads();
        const uint32_t aB = asB + (kt & 1) * ABUFB;
        const uint32_t bB = bsB + (kt & 1) * ABUFB;
#pragma unroll
        for (int k8 = 0; k8 < 2; k8++) {
            uint32_t af[2][4];
            ldsm4(af[0], aB + aOff[0] + k8 * 32);
            ldsm4(af[1], aB + aOff[1] + k8 * 32);
            uint32_t bq[4][4];
#pragma unroll
            for (int ntp = 0; ntp < 4; ntp++)
                ldsm4(bq[ntp], bB + bOff[ntp] + k8 * 32);
#pragma unroll
            for (int mt = 0; mt < 2; mt++)
#pragma unroll
                for (int nt = 0; nt < 8; nt++)
                    mma8(c[mt][nt], af[mt], &bq[nt >> 1][(nt & 1) * 2]);
        }
        __syncthreads();
        issue(kt + 2);
    }

    // ---------------- epilogue ----------------
#pragma unroll
    for (int mt = 0; mt < 2; mt++) {
        const int row0 = m0 + warpM * 32 + mt * 16 + gr;
#pragma unroll
        for (int half = 0; half < 2; half++) {
            const int row = row0 + half * 8;
            const int b = row >> 11;
            const int s = row & 2047;
            float p = 0.0f;
            if (FUSED) { if (which < 2) p = (float)tpos[s]; }
#pragma unroll
            for (int nt = 0; nt < 8; nt++) {
                float v0 = c[mt][nt][half * 2 + 0];
                float v1 = c[mt][nt][half * 2 + 1];
                const int col = n0 + warpN * 64 + nt * 8 + tg * 2;
                if (!FUSED) {
                    outp[(size_t)row * 1024 + col]     = v0;
                    outp[(size_t)row * 1024 + col + 1] = v1;
                } else {
                    const int h  = col >> 6;
                    const int dd = col & 63;
                    if (which < 2) {
                        const int jj = dd >> 1;
                        float freq = 1.0f / powf(10000.0f, (float)(2 * jj) * (1.0f / 64.0f));
                        float sn, cs;
                        sincosf(p * freq, &sn, &cs);
                        float r0 = v0 * cs - v1 * sn;
                        float r1 = v1 * cs + v0 * sn;
                        float* dst = (which == 0) ? g_q : g_k;
                        const int di = ((b * NHEADS + h) * SEQL + s) * DKV + dd;
                        dst[di]     = __uint_as_float(f2tf(r0));
                        dst[di + 1] = __uint_as_float(f2tf(r1));
                    } else {
                        // V transposed: [b,h,d,s]
                        const size_t di = ((size_t)(b * NHEADS + h) * DKV + dd) * SEQL + s;
                        g_v[di]        = __uint_as_float(f2tf(v0));
                        g_v[di + SEQL] = __uint_as_float(f2tf(v1));
                    }
                }
            }
        }
    }
}

// ---------------------------------------------------------------------------
// Flash attention v6: tf32 mma + full ldmatrix (Q, K, P, V), 128-row Q tiles,
// 8 warps, cp.async double-buffered 32-row KV tiles. V is [b,h,d,s].
// smem: Qs 128*68 | Kb 2*32*68 | Vb 2*64*36 | Ps 8*16*68  = 105472 B
// ---------------------------------------------------------------------------
#define QKS 68
#define VST2 36
#define KBOFF (128 * QKS)
#define VBOFF (KBOFF + 2 * 32 * QKS)
#define PSOFF (VBOFF + 2 * 64 * VST2)

__global__ __launch_bounds__(256)
void flash_mma()
{
    extern __shared__ uint32_t sm[];
    uint32_t* Qs = sm;
    uint32_t* Ps = sm + PSOFF;
    const uint32_t smem_u32 = (uint32_t)__cvta_generic_to_shared(sm);

    const float* Q  = g_q;
    const float* K  = g_k;
    const float* Vt = g_v;
    float* out = g_attn;

    const int tid  = threadIdx.x;
    const int lane = tid & 31;
    const int wid  = tid >> 5;
    const int gr   = lane >> 2;
    const int tg   = lane & 3;
    const int qt   = 15 - blockIdx.x;        // heavy tiles first
    const int bh   = blockIdx.y;
    const int b    = bh >> 4;
    const int h    = bh & 15;
    const size_t base = (size_t)bh * SEQL * DKV;
    const int q0   = qt * 128;
    const int rb   = wid * 16;
    uint32_t* Pw   = Ps + wid * 16 * QKS;
    const int njt  = 4 * qt + 4;

    // ldmatrix lane offsets (bytes)
    const int s8 = lane >> 3, j8 = lane & 7;
    const uint32_t qOff = smem_u32 +
        ((rb + (s8 & 1) * 8 + j8) * QKS + (s8 >> 1) * 4) * 4;
    uint32_t kOff[2];
#pragma unroll
    for (int nfp = 0; nfp < 2; nfp++)
        kOff[nfp] = ((nfp * 16 + (s8 >> 1) * 8 + j8) * QKS + (s8 & 1) * 4) * 4;
    uint32_t vOff[4];
#pragma unroll
    for (int ng = 0; ng < 4; ng++)
        vOff[ng] = ((ng * 16 + (s8 >> 1) * 8 + j8) * VST2 + (s8 & 1) * 4) * 4;
    const uint32_t pOff = smem_u32 + (PSOFF + wid * 16 * QKS) * 4 +
        (((s8 & 1) * 8 + j8) * QKS + (s8 >> 1) * 4) * 4;

    // cp.async slots
    const int r0 = tid >> 4, c40 = (tid & 15) * 4;   // K: 32 rows x 16 chunks
    const int r1 = r0 + 16;
    const int vd0 = tid >> 3, vw0 = (tid & 7) * 4;   // Vt: 64 rows x 8 chunks
    const int vd1 = vd0 + 32;

    // Load Q tile (raw bits): 128 x 64
    for (int i = tid; i < 2048; i += 256) {
        const int r = i >> 4, c4 = (i & 15) * 4;
        *(uint4*)&Qs[r * QKS + c4] =
            *(const uint4*)&Q[base + (size_t)(q0 + r) * 64 + c4];
    }

    auto issue = [&](int jt) {
        if (jt < njt) {
            const int buf = jt & 1;
            const size_t krow = base + (size_t)(jt * 32) * 64;
            cpa16(smem_u32 + (KBOFF + buf * 32 * QKS + r0 * QKS + c40) * 4,
                  &K[krow + (size_t)r0 * 64 + c40]);
            cpa16(smem_u32 + (KBOFF + buf * 32 * QKS + r1 * QKS + c40) * 4,
                  &K[krow + (size_t)r1 * 64 + c40]);
            const size_t vcol = base + (size_t)jt * 32;
            cpa16(smem_u32 + (VBOFF + buf * 64 * VST2 + vd0 * VST2 + vw0) * 4,
                  &Vt[vcol + (size_t)vd0 * SEQL + vw0]);
            cpa16(smem_u32 + (VBOFF + buf * 64 * VST2 + vd1 * VST2 + vw0) * 4,
                  &Vt[vcol + (size_t)vd1 * SEQL + vw0]);
        }
        cpa_commit();
    };

    issue(0);
    issue(1);

    float o[8][4];
#pragma unroll
    for (int nf = 0; nf < 8; nf++)
#pragma unroll
        for (int i = 0; i < 4; i++) o[nf][i] = 0.0f;
    float m_i[2] = {-1e30f, -1e30f};
    float l_i[2] = {0.0f, 0.0f};

    for (int jt = 0; jt < njt; jt++) {
        const int buf = jt & 1;
        const uint32_t kbA = smem_u32 + (KBOFF + buf * 32 * QKS) * 4;
        const uint32_t vbA = smem_u32 + (VBOFF + buf * 64 * VST2) * 4;

        cpa_wait<1>();
        __syncthreads();

        // ---- S = Q K^T ----
        float s[4][4];
#pragma unroll
        for (int nf = 0; nf < 4; nf++)
#pragma unroll
            for (int i = 0; i < 4; i++) s[nf][i] = 0.0f;

#pragma unroll
        for (int ks = 0; ks < 8; ks++) {
            uint32_t a[4];
            ldsm4(a, qOff + ks * 32);
            uint32_t kq[2][4];
            ldsm4(kq[0], kbA + kOff[0] + ks * 32);
            ldsm4(kq[1], kbA + kOff[1] + ks * 32);
            mma8(s[0], a, &kq[0][0]);
            mma8(s[1], a, &kq[0][2]);
            mma8(s[2], a, &kq[1][0]);
            mma8(s[3], a, &kq[1][2]);
        }

        // ---- scale + causal mask ----
        const float scale = 0.125f;
        if (jt >= 4 * qt) {
#pragma unroll
            for (int nf = 0; nf < 4; nf++) {
                const int colg = jt * 32 + nf * 8 + tg * 2;
#pragma unroll
                for (int hf = 0; hf < 2; hf++) {
                    const int rowg = q0 + rb + gr + 8 * hf;
                    s[nf][2*hf]   = (colg     > rowg) ? -1e30f : s[nf][2*hf]   * scale;
                    s[nf][2*hf+1] = (colg + 1 > rowg) ? -1e30f : s[nf][2*hf+1] * scale;
                }
            }
        } else {
#pragma unroll
            for (int nf = 0; nf < 4; nf++)
#pragma unroll
                for (int i = 0; i < 4; i++) s[nf][i] *= scale;
        }

        // ---- online softmax ----
        float p[4][4];
#pragma unroll
        for (int hf = 0; hf < 2; hf++) {
            float mx = -1e30f;
#pragma unroll
            for (int nf = 0; nf < 4; nf++)
                mx = fmaxf(mx, fmaxf(s[nf][2*hf], s[nf][2*hf+1]));
            mx = fmaxf(mx, __shfl_xor_sync(0xffffffffu, mx, 1));
            mx = fmaxf(mx, __shfl_xor_sync(0xffffffffu, mx, 2));
            const float mn = fmaxf(m_i[hf], mx);
            const float alpha = __expf(m_i[hf] - mn);
            m_i[hf] = mn;
            float rs = 0.0f;
#pragma unroll
            for (int nf = 0; nf < 4; nf++) {
                float p0 = __expf(s[nf][2*hf]   - mn);
                float p1 = __expf(s[nf][2*hf+1] - mn);
                p[nf][2*hf] = p0; p[nf][2*hf+1] = p1;
                rs += p0 + p1;
            }
            rs += __shfl_xor_sync(0xffffffffu, rs, 1);
            rs += __shfl_xor_sync(0xffffffffu, rs, 2);
            l_i[hf] = l_i[hf] * alpha + rs;
#pragma unroll
            for (int nf = 0; nf < 8; nf++) {
                o[nf][2*hf]   *= alpha;
                o[nf][2*hf+1] *= alpha;
            }
        }

        // ---- stage P (16x32) in warp-private smem ----
#pragma unroll
        for (int nf = 0; nf < 4; nf++) {
            const int col = nf * 8 + tg * 2;
            *(uint2*)&Pw[gr * QKS + col]       = make_uint2(f2tf(p[nf][0]), f2tf(p[nf][1]));
            *(uint2*)&Pw[(gr + 8) * QKS + col] = make_uint2(f2tf(p[nf][2]), f2tf(p[nf][3]));
        }
        __syncwarp();

        // ---- O += P V  (P and V both via ldmatrix) ----
#pragma unroll
        for (int ks = 0; ks < 4; ks++) {
            uint32_t a[4];
            ldsm4(a, pOff + ks * 32);
#pragma unroll
            for (int ng = 0; ng < 4; ng++) {
                uint32_t vq[4];
                ldsm4(vq, vbA + vOff[ng] + ks * 32);
                mma8(o[2*ng],     a, &vq[0]);
                mma8(o[2*ng + 1], a, &vq[2]);
            }
        }

        __syncthreads();
        issue(jt + 2);
    }

    // ---- normalize + store [b, s, h*64 + d] (tf32 bits for out-proj) ----
#pragma unroll
    for (int hf = 0; hf < 2; hf++) {
        const float inv = 1.0f / l_i[hf];
        const int srow = q0 + rb + gr + 8 * hf;
        const size_t ob = (size_t)(b * SEQL + srow) * 1024 + h * 64;
#pragma unroll
        for (int nf = 0; nf < 8; nf++) {
            const int col = nf * 8 + tg * 2;
            float2 v2 = make_float2(
                __uint_as_float(f2tf(o[nf][2*hf]   * inv)),
                __uint_as_float(f2tf(o[nf][2*hf+1] * inv)));
            *(float2*)&out[ob + col] = v2;
        }
    }
}

// ---------------------------------------------------------------------------
extern "C" void kernel_launch(void* const* d_in, const int* in_sizes, int n_in,
                              void* d_out, int out_size)
{
    const float* x  = (const float*)d_in[0];
    const float* wq = (const float*)d_in[1];
    const float* wk = (const float*)d_in[2];
    const float* wv = (const float*)d_in[3];
    const float* wo = (const float*)d_in[4];
    const int*   tp = (const int*)d_in[5];
    float* out = (float*)d_out;

    const int flash_smem = (PSOFF + 8 * 16 * QKS) * (int)sizeof(uint32_t); // 105472
    cudaFuncSetAttribute(flash_mma, cudaFuncAttributeMaxDynamicSharedMemorySize,
                         flash_smem);

    preround<<<2048, 256>>>(x, wq, wk, wv, wo);
    proj_cp<1><<<dim3(24, 32), 256>>>(tp, nullptr);          // QKV fused
    flash_mma<<<dim3(16, 32), 256, flash_smem>>>();
    proj_cp<0><<<dim3(8, 32), 256>>>(nullptr, out);          // output proj
}

// round 11
// speedup vs baseline: 3.4117x; 1.0001x over previous
#include <cuda_runtime.h>
#include <math.h>
#include <stdint.h>

#define D_MODEL 1024
#define NHEADS  16
#define DKV     64
#define SEQL    2048
#define BATCH   2

// Scratch (allocation-free rule: __device__ globals)
__device__ float g_xr[4096*1024];                // x, tf32-rounded bits
__device__ float g_w[3*1024*1024];               // wq|wk|wv rounded
__device__ float g_wor[1024*1024];               // wo rounded
__device__ float g_q[BATCH*NHEADS*SEQL*DKV];     // [b,h,s,d]  tf32 bits
__device__ float g_k[BATCH*NHEADS*SEQL*DKV];     // [b,h,s,d]  tf32 bits
__device__ float g_v[BATCH*NHEADS*SEQL*DKV];     // [b,h,d,s]  tf32 bits (TRANSPOSED)
__device__ float g_attn[BATCH*SEQL*D_MODEL];     // [b,s,h*64+d] tf32 bits

// ---------------------------------------------------------------------------
// tf32 / mma / ldmatrix / cp.async helpers
// ---------------------------------------------------------------------------
__device__ __forceinline__ uint32_t f2tf(float f) {
    uint32_t r;
    asm("cvt.rna.tf32.f32 %0, %1;" : "=r"(r) : "f"(f));
    return r;
}

__device__ __forceinline__ void mma8(float* c, const uint32_t* a, const uint32_t* b) {
    asm volatile(
        "mma.sync.aligned.m16n8k8.row.col.f32.tf32.tf32.f32 "
        "{%0,%1,%2,%3}, {%4,%5,%6,%7}, {%8,%9}, {%0,%1,%2,%3};"
        : "+f"(c[0]), "+f"(c[1]), "+f"(c[2]), "+f"(c[3])
        : "r"(a[0]), "r"(a[1]), "r"(a[2]), "r"(a[3]), "r"(b[0]), "r"(b[1]));
}

__device__ __forceinline__ void ldsm4(uint32_t* r, uint32_t addr) {
    asm volatile("ldmatrix.sync.aligned.m8n8.x4.shared.b16 {%0,%1,%2,%3}, [%4];"
        : "=r"(r[0]), "=r"(r[1]), "=r"(r[2]), "=r"(r[3]) : "r"(addr));
}

__device__ __forceinline__ void cpa16(uint32_t dst, const void* src) {
    asm volatile("cp.async.ca.shared.global [%0], [%1], 16;" :: "r"(dst), "l"(src));
}
__device__ __forceinline__ void cpa_commit() {
    asm volatile("cp.async.commit_group;");
}
template<int N>
__device__ __forceinline__ void cpa_wait() {
    asm volatile("cp.async.wait_group %0;" :: "n"(N));
}

// ---------------------------------------------------------------------------
// Pre-round: x, wq|wk|wv, wo -> tf32 bits in scratch (grid-stride, float4)
// ---------------------------------------------------------------------------
__device__ __forceinline__ void round4(float* dst, const float* src, int i) {
    float4 a = ((const float4*)src)[i];
    uint4 r = make_uint4(f2tf(a.x), f2tf(a.y), f2tf(a.z), f2tf(a.w));
    ((uint4*)dst)[i] = r;
}

__global__ __launch_bounds__(256)
void preround(const float* __restrict__ x,  const float* __restrict__ wq,
              const float* __restrict__ wk, const float* __restrict__ wv,
              const float* __restrict__ wo)
{
    const int t = blockIdx.x * 256 + threadIdx.x;
    const int stride = gridDim.x * 256;
    for (int i = t; i < 1048576; i += stride) round4(g_xr, x, i);
    for (int i = t; i < 262144;  i += stride) round4(g_w,            wq, i);
    for (int i = t; i < 262144;  i += stride) round4(g_w + 1048576,  wk, i);
    for (int i = t; i < 262144;  i += stride) round4(g_w + 2097152,  wv, i);
    for (int i = t; i < 262144;  i += stride) round4(g_wor,          wo, i);
}

// ---------------------------------------------------------------------------
// Projection GEMM: 3-stage cp.async ring, ONE barrier per k-iter.
//   C[m,n] = sum_k A[m,k]*W[n,k]; block 128x128, BK=16, 8 warps.
// FUSED=1: QKV fused; FUSED=0: out-projection.
// dyn smem: As 3*128*20 | Bs 3*128*20 = 61440 B
// ---------------------------------------------------------------------------
#define LDA 20
#define ABUFB (128 * LDA * 4)   // bytes per stage buffer
#define PROJ_SMEM (6 * 128 * LDA * 4)

template<int FUSED>
__global__ __launch_bounds__(256)
void proj_cp(const int* __restrict__ tpos, float* __restrict__ outp)
{
    extern __shared__ uint32_t psm[];
    const uint32_t asB = (uint32_t)__cvta_generic_to_shared(psm);
    const uint32_t bsB = asB + 3 * ABUFB;

    const int tid   = threadIdx.x;
    const int lane  = tid & 31;
    const int wid   = tid >> 5;
    const int warpM = wid >> 1;
    const int warpN = wid & 1;
    const int gr    = lane >> 2;
    const int tg    = lane & 3;
    const int m0    = blockIdx.y * 128;

    int which, n0;
    const float *A, *W;
    if (FUSED) {
        which = blockIdx.x >> 3;
        n0 = (blockIdx.x & 7) * 128;
        A = g_xr;
        W = g_w + (size_t)which * 1048576;
    } else {
        which = -1;
        n0 = blockIdx.x * 128;
        A = g_attn;
        W = g_wor;
    }

    const int rA0 = tid >> 2, wA0 = (tid & 3) * 4;   // row 0..63
    const int rA1 = rA0 + 64;

    // ldmatrix per-lane offsets (bytes within one buffer)
    const int s8 = lane >> 3, j8 = lane & 7;
    uint32_t aOff[2], bOff[4];
#pragma unroll
    for (int mt = 0; mt < 2; mt++)
        aOff[mt] = ((warpM * 32 + mt * 16 + (s8 & 1) * 8 + j8) * LDA + (s8 >> 1) * 4) * 4;
#pragma unroll
    for (int ntp = 0; ntp < 4; ntp++)
        bOff[ntp] = ((warpN * 64 + ntp * 16 + (s8 >> 1) * 8 + j8) * LDA + (s8 & 1) * 4) * 4;

    auto issue = [&](int kt) {
        if (kt < 64) {
            const int buf = kt % 3;
            const float* a = A + (size_t)(m0 + rA0) * 1024 + kt * 16 + wA0;
            cpa16(asB + buf * ABUFB + (rA0 * LDA + wA0) * 4, a);
            cpa16(asB + buf * ABUFB + (rA1 * LDA + wA0) * 4, a + 64 * 1024);
            const float* w = W + (size_t)(n0 + rA0) * 1024 + kt * 16 + wA0;
            cpa16(bsB + buf * ABUFB + (rA0 * LDA + wA0) * 4, w);
            cpa16(bsB + buf * ABUFB + (rA1 * LDA + wA0) * 4, w + 64 * 1024);
        }
        cpa_commit();
    };

    float c[2][8][4];
#pragma unroll
    for (int mt = 0; mt < 2; mt++)
#pragma unroll
        for (int nt = 0; nt < 8; nt++)
#pragma unroll
            for (int i = 0; i < 4; i++) c[mt][nt][i] = 0.0f;

    issue(0);
    issue(1);

    for (int kt = 0; kt < 64; kt++) {
        cpa_wait<1>();        // stage kt landed (kt+1 may be in flight)
        __syncthreads();      // visible to all
        const int buf = kt % 3;
        const uint32_t aB = asB + buf * ABUFB;
        const uint32_t bB = bsB + buf * ABUFB;
#pragma unroll
        for (int k8 = 0; k8 < 2; k8++) {
            uint32_t af[2][4];
            ldsm4(af[0], aB + aOff[0] + k8 * 32);
            ldsm4(af[1], aB + aOff[1] + k8 * 32);
            uint32_t bq[4][4];
#pragma unroll
            for (int ntp = 0; ntp < 4; ntp++)
                ldsm4(bq[ntp], bB + bOff[ntp] + k8 * 32);
#pragma unroll
            for (int mt = 0; mt < 2; mt++)
#pragma unroll
                for (int nt = 0; nt < 8; nt++)
                    mma8(c[mt][nt], af[mt], &bq[nt >> 1][(nt & 1) * 2]);
        }
        // issue(kt+2) overwrites buffer (kt+2)%3 = (kt-1)%3, whose reads all
        // completed before this iteration's top barrier.
        issue(kt + 2);
    }

    // ---------------- epilogue ----------------
#pragma unroll
    for (int mt = 0; mt < 2; mt++) {
        const int row0 = m0 + warpM * 32 + mt * 16 + gr;
#pragma unroll
        for (int half = 0; half < 2; half++) {
            const int row = row0 + half * 8;
            const int b = row >> 11;
            const int s = row & 2047;
            float p = 0.0f;
            if (FUSED) { if (which < 2) p = (float)tpos[s]; }
#pragma unroll
            for (int nt = 0; nt < 8; nt++) {
                float v0 = c[mt][nt][half * 2 + 0];
                float v1 = c[mt][nt][half * 2 + 1];
                const int col = n0 + warpN * 64 + nt * 8 + tg * 2;
                if (!FUSED) {
                    outp[(size_t)row * 1024 + col]     = v0;
                    outp[(size_t)row * 1024 + col + 1] = v1;
                } else {
                    const int h  = col >> 6;
                    const int dd = col & 63;
                    if (which < 2) {
                        const int jj = dd >> 1;
                        float freq = 1.0f / powf(10000.0f, (float)(2 * jj) * (1.0f / 64.0f));
                        float sn, cs;
                        sincosf(p * freq, &sn, &cs);
                        float r0 = v0 * cs - v1 * sn;
                        float r1 = v1 * cs + v0 * sn;
                        float* dst = (which == 0) ? g_q : g_k;
                        const int di = ((b * NHEADS + h) * SEQL + s) * DKV + dd;
                        dst[di]     = __uint_as_float(f2tf(r0));
                        dst[di + 1] = __uint_as_float(f2tf(r1));
                    } else {
                        // V transposed: [b,h,d,s]
                        const size_t di = ((size_t)(b * NHEADS + h) * DKV + dd) * SEQL + s;
                        g_v[di]        = __uint_as_float(f2tf(v0));
                        g_v[di + SEQL] = __uint_as_float(f2tf(v1));
                    }
                }
            }
        }
    }
}

// ---------------------------------------------------------------------------
// Flash attention v7: tf32 mma + full ldmatrix, 128-row Q tiles, 8 warps,
// 3-stage cp.async KV ring, ONE barrier per kv-iter. V is [b,h,d,s].
// smem words: Qs 128*68 | Kb 3*32*68 | Vb 3*64*36 | Ps 8*16*36  = 107008 B
// ---------------------------------------------------------------------------
#define QKS 68
#define VST2 36
#define PST 36
#define KBOFF (128 * QKS)
#define VBOFF (KBOFF + 3 * 32 * QKS)
#define PSOFF (VBOFF + 3 * 64 * VST2)
#define FLASH_SMEM ((PSOFF + 8 * 16 * PST) * 4)

__global__ __launch_bounds__(256)
void flash_mma()
{
    extern __shared__ uint32_t sm[];
    uint32_t* Qs = sm;
    uint32_t* Ps = sm + PSOFF;
    const uint32_t smem_u32 = (uint32_t)__cvta_generic_to_shared(sm);

    const float* Q  = g_q;
    const float* K  = g_k;
    const float* Vt = g_v;
    float* out = g_attn;

    const int tid  = threadIdx.x;
    const int lane = tid & 31;
    const int wid  = tid >> 5;
    const int gr   = lane >> 2;
    const int tg   = lane & 3;
    const int qt   = 15 - blockIdx.x;        // heavy tiles first
    const int bh   = blockIdx.y;
    const int b    = bh >> 4;
    const int h    = bh & 15;
    const size_t base = (size_t)bh * SEQL * DKV;
    const int q0   = qt * 128;
    const int rb   = wid * 16;
    uint32_t* Pw   = Ps + wid * 16 * PST;
    const int njt  = 4 * qt + 4;

    // ldmatrix lane offsets (bytes)
    const int s8 = lane >> 3, j8 = lane & 7;
    const uint32_t qOff = smem_u32 +
        ((rb + (s8 & 1) * 8 + j8) * QKS + (s8 >> 1) * 4) * 4;
    uint32_t kOff[2];
#pragma unroll
    for (int nfp = 0; nfp < 2; nfp++)
        kOff[nfp] = ((nfp * 16 + (s8 >> 1) * 8 + j8) * QKS + (s8 & 1) * 4) * 4;
    uint32_t vOff[4];
#pragma unroll
    for (int ng = 0; ng < 4; ng++)
        vOff[ng] = ((ng * 16 + (s8 >> 1) * 8 + j8) * VST2 + (s8 & 1) * 4) * 4;
    const uint32_t pOff = smem_u32 + (PSOFF + wid * 16 * PST) * 4 +
        (((s8 & 1) * 8 + j8) * PST + (s8 >> 1) * 4) * 4;

    // cp.async slots
    const int r0 = tid >> 4, c40 = (tid & 15) * 4;   // K: 32 rows x 16 chunks
    const int r1 = r0 + 16;
    const int vd0 = tid >> 3, vw0 = (tid & 7) * 4;   // Vt: 64 rows x 8 chunks
    const int vd1 = vd0 + 32;

    // Load Q tile (raw bits): 128 x 64
    for (int i = tid; i < 2048; i += 256) {
        const int r = i >> 4, c4 = (i & 15) * 4;
        *(uint4*)&Qs[r * QKS + c4] =
            *(const uint4*)&Q[base + (size_t)(q0 + r) * 64 + c4];
    }

    auto issue = [&](int jt) {
        if (jt < njt) {
            const int buf = jt % 3;
            const size_t krow = base + (size_t)(jt * 32) * 64;
            cpa16(smem_u32 + (KBOFF + buf * 32 * QKS + r0 * QKS + c40) * 4,
                  &K[krow + (size_t)r0 * 64 + c40]);
            cpa16(smem_u32 + (KBOFF + buf * 32 * QKS + r1 * QKS + c40) * 4,
                  &K[krow + (size_t)r1 * 64 + c40]);
            const size_t vcol = base + (size_t)jt * 32;
            cpa16(smem_u32 + (VBOFF + buf * 64 * VST2 + vd0 * VST2 + vw0) * 4,
                  &Vt[vcol + (size_t)vd0 * SEQL + vw0]);
            cpa16(smem_u32 + (VBOFF + buf * 64 * VST2 + vd1 * VST2 + vw0) * 4,
                  &Vt[vcol + (size_t)vd1 * SEQL + vw0]);
        }
        cpa_commit();
    };

    issue(0);
    issue(1);

    float o[8][4];
#pragma unroll
    for (int nf = 0; nf < 8; nf++)
#pragma unroll
        for (int i = 0; i < 4; i++) o[nf][i] = 0.0f;
    float m_i[2] = {-1e30f, -1e30f};
    float l_i[2] = {0.0f, 0.0f};

    for (int jt = 0; jt < njt; jt++) {
        const int buf = jt % 3;
        const uint32_t kbA = smem_u32 + (KBOFF + buf * 32 * QKS) * 4;
        const uint32_t vbA = smem_u32 + (VBOFF + buf * 64 * VST2) * 4;

        cpa_wait<1>();        // stage jt landed
        __syncthreads();      // visible; also covers Q store (iter 0)

        // ---- S = Q K^T ----
        float s[4][4];
#pragma unroll
        for (int nf = 0; nf < 4; nf++)
#pragma unroll
            for (int i = 0; i < 4; i++) s[nf][i] = 0.0f;

#pragma unroll
        for (int ks = 0; ks < 8; ks++) {
            uint32_t a[4];
            ldsm4(a, qOff + ks * 32);
            uint32_t kq[2][4];
            ldsm4(kq[0], kbA + kOff[0] + ks * 32);
            ldsm4(kq[1], kbA + kOff[1] + ks * 32);
            mma8(s[0], a, &kq[0][0]);
            mma8(s[1], a, &kq[0][2]);
            mma8(s[2], a, &kq[1][0]);
            mma8(s[3], a, &kq[1][2]);
        }

        // ---- scale + causal mask ----
        const float scale = 0.125f;
        if (jt >= 4 * qt) {
#pragma unroll
            for (int nf = 0; nf < 4; nf++) {
                const int colg = jt * 32 + nf * 8 + tg * 2;
#pragma unroll
                for (int hf = 0; hf < 2; hf++) {
                    const int rowg = q0 + rb + gr + 8 * hf;
                    s[nf][2*hf]   = (colg     > rowg) ? -1e30f : s[nf][2*hf]   * scale;
                    s[nf][2*hf+1] = (colg + 1 > rowg) ? -1e30f : s[nf][2*hf+1] * scale;
                }
            }
        } else {
#pragma unroll
            for (int nf = 0; nf < 4; nf++)
#pragma unroll
                for (int i = 0; i < 4; i++) s[nf][i] *= scale;
        }

        // ---- online softmax ----
        float p[4][4];
#pragma unroll
        for (int hf = 0; hf < 2; hf++) {
            float mx = -1e30f;
#pragma unroll
            for (int nf = 0; nf < 4; nf++)
                mx = fmaxf(mx, fmaxf(s[nf][2*hf], s[nf][2*hf+1]));
            mx = fmaxf(mx, __shfl_xor_sync(0xffffffffu, mx, 1));
            mx = fmaxf(mx, __shfl_xor_sync(0xffffffffu, mx, 2));
            const float mn = fmaxf(m_i[hf], mx);
            const float alpha = __expf(m_i[hf] - mn);
            m_i[hf] = mn;
            float rs = 0.0f;
#pragma unroll
            for (int nf = 0; nf < 4; nf++) {
                float p0 = __expf(s[nf][2*hf]   - mn);
                float p1 = __expf(s[nf][2*hf+1] - mn);
                p[nf][2*hf] = p0; p[nf][2*hf+1] = p1;
                rs += p0 + p1;
            }
            rs += __shfl_xor_sync(0xffffffffu, rs, 1);
            rs += __shfl_xor_sync(0xffffffffu, rs, 2);
            l_i[hf] = l_i[hf] * alpha + rs;
#pragma unroll
            for (int nf = 0; nf < 8; nf++) {
                o[nf][2*hf]   *= alpha;
                o[nf][2*hf+1] *= alpha;
            }
        }

        // ---- stage P (16x32) in warp-private smem ----
#pragma unroll
        for (int nf = 0; nf < 4; nf++) {
            const int col = nf * 8 + tg * 2;
            *(uint2*)&Pw[gr * PST + col]       = make_uint2(f2tf(p[nf][0]), f2tf(p[nf][1]));
            *(uint2*)&Pw[(gr + 8) * PST + col] = make_uint2(f2tf(p[nf][2]), f2tf(p[nf][3]));
        }
        __syncwarp();

        // ---- O += P V ----
#pragma unroll
        for (int ks = 0; ks < 4; ks++) {
            uint32_t a[4];
            ldsm4(a, pOff + ks * 32);
#pragma unroll
            for (int ng = 0; ng < 4; ng++) {
                uint32_t vq[4];
                ldsm4(vq, vbA + vOff[ng] + ks * 32);
                mma8(o[2*ng],     a, &vq[0]);
                mma8(o[2*ng + 1], a, &vq[2]);
            }
        }

        // refill buffer (jt+2)%3 = (jt-1)%3: its reads finished before this
        // iteration's top barrier.
        issue(jt + 2);
    }

    // ---- normalize + store [b, s, h*64 + d] (tf32 bits for out-proj) ----
#pragma unroll
    for (int hf = 0; hf < 2; hf++) {
        const float inv = 1.0f / l_i[hf];
        const int srow = q0 + rb + gr + 8 * hf;
        const size_t ob = (size_t)(b * SEQL + srow) * 1024 + h * 64;
#pragma unroll
        for (int nf = 0; nf < 8; nf++) {
            const int col = nf * 8 + tg * 2;
            float2 v2 = make_float2(
                __uint_as_float(f2tf(o[nf][2*hf]   * inv)),
                __uint_as_float(f2tf(o[nf][2*hf+1] * inv)));
            *(float2*)&out[ob + col] = v2;
        }
    }
}

// ---------------------------------------------------------------------------
extern "C" void kernel_launch(void* const* d_in, const int* in_sizes, int n_in,
                              void* d_out, int out_size)
{
    const float* x  = (const float*)d_in[0];
    const float* wq = (const float*)d_in[1];
    const float* wk = (const float*)d_in[2];
    const float* wv = (const float*)d_in[3];
    const float* wo = (const float*)d_in[4];
    const int*   tp = (const int*)d_in[5];
    float* out = (float*)d_out;

    cudaFuncSetAttribute(proj_cp<1>, cudaFuncAttributeMaxDynamicSharedMemorySize,
                         PROJ_SMEM);
    cudaFuncSetAttribute(proj_cp<0>, cudaFuncAttributeMaxDynamicSharedMemorySize,
                         PROJ_SMEM);
    cudaFuncSetAttribute(flash_mma, cudaFuncAttributeMaxDynamicSharedMemorySize,
                         FLASH_SMEM);

    preround<<<2048, 256>>>(x, wq, wk, wv, wo);
    proj_cp<1><<<dim3(24, 32), 256, PROJ_SMEM>>>(tp, nullptr);   // QKV fused
    flash_mma<<<dim3(16, 32), 256, FLASH_SMEM>>>();
    proj_cp<0><<<dim3(8, 32), 256, PROJ_SMEM>>>(nullptr, out);   // output proj
}